// round 1
// baseline (speedup 1.0000x reference)
#include <cuda_runtime.h>

#define NB 512
#define NF 64
#define NP 2016
#define NE 32
#define NH 128
#define MT 32   // batch rows per CTA

__device__ __forceinline__ float smooth_z(float z) {
    // GAMMA = 1: (-2)z^3 + 1.5z + 0.5, clamped at +/-0.5
    float s = fmaf(-2.0f * z * z, z, fmaf(1.5f, z, 0.5f));
    s = (z <= -0.5f) ? 0.0f : s;
    s = (z >=  0.5f) ? 1.0f : s;
    return s;
}

// ---------------------------------------------------------------------------
// Pair-effects kernel: one CTA = (32 batch rows) x (one pair p)
//   e[32,64] (gather) -> relu(e@w0+b0)[32,128] -> relu(h@w1+b1)[32,128]
//   -> dot w2 + b2 -> * smooth_z(z_p) -> atomicAdd into out[b]
// ---------------------------------------------------------------------------
__global__ __launch_bounds__(256)
void pair_kernel(const int*   __restrict__ pairs,      // [B,P,2]
                 const float* __restrict__ emb,        // [4096,32]
                 const float* __restrict__ pw0,        // [P,64,128]
                 const float* __restrict__ pw1,        // [P,128,128]
                 const float* __restrict__ pw2,        // [P,128,1]
                 const float* __restrict__ pb0,        // [P,128]
                 const float* __restrict__ pb1,        // [P,128]
                 const float* __restrict__ pb2,        // [P,1]
                 const float* __restrict__ z_pairs,    // [P]
                 const int*   __restrict__ pairs_list, // [P,2]
                 const int*   __restrict__ feat_off,   // [F]
                 float*       __restrict__ out)        // [B]
{
    __shared__ float e_s[MT * 64];
    __shared__ float w_s[32 * 128];
    __shared__ float h_s[MT * 128];
    __shared__ float w2_s[128];
    __shared__ float red_s[MT * 33];

    const int p   = blockIdx.y;
    const int b0  = blockIdx.x * MT;
    const int tid = threadIdx.x;

    const int fi   = pairs_list[2 * p + 0];
    const int fj   = pairs_list[2 * p + 1];
    const int offi = feat_off[fi];
    const int offj = feat_off[fj];

    // Gather concat(emb[bin_i + off_i], emb[bin_j + off_j]) -> e_s[32,64]
    for (int t = tid; t < MT * 64; t += 256) {
        int r = t >> 6, c = t & 63;
        int side = c >> 5, cc = c & 31;
        int bin  = pairs[(((size_t)(b0 + r)) * NP + p) * 2 + side];
        int row  = bin + (side ? offj : offi);
        e_s[t] = emb[row * NE + cc];
    }

    const int cx  = tid & 31;   // 32 col groups of 4
    const int ry  = tid >> 5;   // 8 row groups of 4
    const int col = cx * 4;
    const int r0  = ry * 4;

    // ---- layer 0: [32,64] @ [64,128] ----
    float acc[4][4];
    #pragma unroll
    for (int i = 0; i < 4; i++)
        #pragma unroll
        for (int j = 0; j < 4; j++) acc[i][j] = 0.0f;

    const float* w0p = pw0 + (size_t)p * 64 * 128;
    #pragma unroll 1
    for (int kc = 0; kc < 64; kc += 32) {
        __syncthreads();
        #pragma unroll
        for (int t = tid; t < 32 * 128; t += 256) w_s[t] = w0p[kc * 128 + t];
        __syncthreads();
        #pragma unroll
        for (int k = 0; k < 32; k++) {
            float a0 = e_s[(r0 + 0) * 64 + kc + k];
            float a1 = e_s[(r0 + 1) * 64 + kc + k];
            float a2 = e_s[(r0 + 2) * 64 + kc + k];
            float a3 = e_s[(r0 + 3) * 64 + kc + k];
            float4 bv = *(const float4*)&w_s[k * 128 + col];
            acc[0][0] = fmaf(a0, bv.x, acc[0][0]);
            acc[0][1] = fmaf(a0, bv.y, acc[0][1]);
            acc[0][2] = fmaf(a0, bv.z, acc[0][2]);
            acc[0][3] = fmaf(a0, bv.w, acc[0][3]);
            acc[1][0] = fmaf(a1, bv.x, acc[1][0]);
            acc[1][1] = fmaf(a1, bv.y, acc[1][1]);
            acc[1][2] = fmaf(a1, bv.z, acc[1][2]);
            acc[1][3] = fmaf(a1, bv.w, acc[1][3]);
            acc[2][0] = fmaf(a2, bv.x, acc[2][0]);
            acc[2][1] = fmaf(a2, bv.y, acc[2][1]);
            acc[2][2] = fmaf(a2, bv.z, acc[2][2]);
            acc[2][3] = fmaf(a2, bv.w, acc[2][3]);
            acc[3][0] = fmaf(a3, bv.x, acc[3][0]);
            acc[3][1] = fmaf(a3, bv.y, acc[3][1]);
            acc[3][2] = fmaf(a3, bv.z, acc[3][2]);
            acc[3][3] = fmaf(a3, bv.w, acc[3][3]);
        }
    }

    // bias + relu -> h_s
    {
        const float* b0p = pb0 + (size_t)p * NH;
        #pragma unroll
        for (int i = 0; i < 4; i++)
            #pragma unroll
            for (int j = 0; j < 4; j++) {
                float v = acc[i][j] + b0p[col + j];
                h_s[(r0 + i) * 128 + col + j] = fmaxf(v, 0.0f);
            }
    }

    // ---- layer 1: [32,128] @ [128,128] ----
    float acc2[4][4];
    #pragma unroll
    for (int i = 0; i < 4; i++)
        #pragma unroll
        for (int j = 0; j < 4; j++) acc2[i][j] = 0.0f;

    const float* w1p = pw1 + (size_t)p * 128 * 128;
    #pragma unroll 1
    for (int kc = 0; kc < 128; kc += 32) {
        __syncthreads();
        #pragma unroll
        for (int t = tid; t < 32 * 128; t += 256) w_s[t] = w1p[kc * 128 + t];
        __syncthreads();
        #pragma unroll
        for (int k = 0; k < 32; k++) {
            float a0 = h_s[(r0 + 0) * 128 + kc + k];
            float a1 = h_s[(r0 + 1) * 128 + kc + k];
            float a2 = h_s[(r0 + 2) * 128 + kc + k];
            float a3 = h_s[(r0 + 3) * 128 + kc + k];
            float4 bv = *(const float4*)&w_s[k * 128 + col];
            acc2[0][0] = fmaf(a0, bv.x, acc2[0][0]);
            acc2[0][1] = fmaf(a0, bv.y, acc2[0][1]);
            acc2[0][2] = fmaf(a0, bv.z, acc2[0][2]);
            acc2[0][3] = fmaf(a0, bv.w, acc2[0][3]);
            acc2[1][0] = fmaf(a1, bv.x, acc2[1][0]);
            acc2[1][1] = fmaf(a1, bv.y, acc2[1][1]);
            acc2[1][2] = fmaf(a1, bv.z, acc2[1][2]);
            acc2[1][3] = fmaf(a1, bv.w, acc2[1][3]);
            acc2[2][0] = fmaf(a2, bv.x, acc2[2][0]);
            acc2[2][1] = fmaf(a2, bv.y, acc2[2][1]);
            acc2[2][2] = fmaf(a2, bv.z, acc2[2][2]);
            acc2[2][3] = fmaf(a2, bv.w, acc2[2][3]);
            acc2[3][0] = fmaf(a3, bv.x, acc2[3][0]);
            acc2[3][1] = fmaf(a3, bv.y, acc2[3][1]);
            acc2[3][2] = fmaf(a3, bv.z, acc2[3][2]);
            acc2[3][3] = fmaf(a3, bv.w, acc2[3][3]);
        }
    }

    // ---- layer 2 (dot with w2) + smooth_z scale + atomic accumulate ----
    if (tid < 128) w2_s[tid] = pw2[(size_t)p * NH + tid];
    __syncthreads();

    {
        const float* b1p = pb1 + (size_t)p * NH;
        #pragma unroll
        for (int i = 0; i < 4; i++) {
            float si = 0.0f;
            #pragma unroll
            for (int j = 0; j < 4; j++) {
                float v = fmaxf(acc2[i][j] + b1p[col + j], 0.0f);
                si = fmaf(v, w2_s[col + j], si);
            }
            red_s[(r0 + i) * 33 + cx] = si;
        }
    }
    __syncthreads();

    if (tid < MT) {
        float sum = 0.0f;
        #pragma unroll
        for (int t = 0; t < 32; t++) sum += red_s[tid * 33 + t];
        float zp = smooth_z(z_pairs[p]);
        atomicAdd(&out[b0 + tid], zp * (sum + pb2[p]));
    }
}

// ---------------------------------------------------------------------------
// Main-effects kernel: one CTA = (32 batch rows) x (one feature f)
//   e[32,32] -> relu(e@w0+b0)[32,128] -> relu(h@w1+b1)[32,128] -> dot w2
// ---------------------------------------------------------------------------
__global__ __launch_bounds__(256)
void main_kernel(const int*   __restrict__ mains,     // [B,F]
                 const float* __restrict__ emb,       // [4096,32]
                 const float* __restrict__ mw0,       // [F,32,128]
                 const float* __restrict__ mw1,       // [F,128,128]
                 const float* __restrict__ mw2,       // [F,128,1]
                 const float* __restrict__ mb0,       // [F,128]
                 const float* __restrict__ mb1,       // [F,128]
                 const float* __restrict__ mb2,       // [F,1]
                 const float* __restrict__ z_main,    // [F]
                 const int*   __restrict__ feat_off,  // [F]
                 float*       __restrict__ out)       // [B]
{
    __shared__ float e_s[MT * 32];
    __shared__ float w_s[32 * 128];
    __shared__ float h_s[MT * 128];
    __shared__ float w2_s[128];
    __shared__ float red_s[MT * 33];

    const int f   = blockIdx.y;
    const int b0  = blockIdx.x * MT;
    const int tid = threadIdx.x;
    const int off = feat_off[f];

    for (int t = tid; t < MT * 32; t += 256) {
        int r = t >> 5, c = t & 31;
        int bin = mains[(size_t)(b0 + r) * NF + f];
        e_s[t] = emb[(bin + off) * NE + c];
    }

    const int cx  = tid & 31;
    const int ry  = tid >> 5;
    const int col = cx * 4;
    const int r0  = ry * 4;

    // ---- layer 0: [32,32] @ [32,128] (single K chunk) ----
    float acc[4][4];
    #pragma unroll
    for (int i = 0; i < 4; i++)
        #pragma unroll
        for (int j = 0; j < 4; j++) acc[i][j] = 0.0f;

    const float* w0p = mw0 + (size_t)f * 32 * 128;
    __syncthreads();
    #pragma unroll
    for (int t = tid; t < 32 * 128; t += 256) w_s[t] = w0p[t];
    __syncthreads();
    #pragma unroll
    for (int k = 0; k < 32; k++) {
        float a0 = e_s[(r0 + 0) * 32 + k];
        float a1 = e_s[(r0 + 1) * 32 + k];
        float a2 = e_s[(r0 + 2) * 32 + k];
        float a3 = e_s[(r0 + 3) * 32 + k];
        float4 bv = *(const float4*)&w_s[k * 128 + col];
        acc[0][0] = fmaf(a0, bv.x, acc[0][0]);
        acc[0][1] = fmaf(a0, bv.y, acc[0][1]);
        acc[0][2] = fmaf(a0, bv.z, acc[0][2]);
        acc[0][3] = fmaf(a0, bv.w, acc[0][3]);
        acc[1][0] = fmaf(a1, bv.x, acc[1][0]);
        acc[1][1] = fmaf(a1, bv.y, acc[1][1]);
        acc[1][2] = fmaf(a1, bv.z, acc[1][2]);
        acc[1][3] = fmaf(a1, bv.w, acc[1][3]);
        acc[2][0] = fmaf(a2, bv.x, acc[2][0]);
        acc[2][1] = fmaf(a2, bv.y, acc[2][1]);
        acc[2][2] = fmaf(a2, bv.z, acc[2][2]);
        acc[2][3] = fmaf(a2, bv.w, acc[2][3]);
        acc[3][0] = fmaf(a3, bv.x, acc[3][0]);
        acc[3][1] = fmaf(a3, bv.y, acc[3][1]);
        acc[3][2] = fmaf(a3, bv.z, acc[3][2]);
        acc[3][3] = fmaf(a3, bv.w, acc[3][3]);
    }

    {
        const float* b0p = mb0 + (size_t)f * NH;
        #pragma unroll
        for (int i = 0; i < 4; i++)
            #pragma unroll
            for (int j = 0; j < 4; j++) {
                float v = acc[i][j] + b0p[col + j];
                h_s[(r0 + i) * 128 + col + j] = fmaxf(v, 0.0f);
            }
    }

    // ---- layer 1: [32,128] @ [128,128] ----
    float acc2[4][4];
    #pragma unroll
    for (int i = 0; i < 4; i++)
        #pragma unroll
        for (int j = 0; j < 4; j++) acc2[i][j] = 0.0f;

    const float* w1p = mw1 + (size_t)f * 128 * 128;
    #pragma unroll 1
    for (int kc = 0; kc < 128; kc += 32) {
        __syncthreads();
        #pragma unroll
        for (int t = tid; t < 32 * 128; t += 256) w_s[t] = w1p[kc * 128 + t];
        __syncthreads();
        #pragma unroll
        for (int k = 0; k < 32; k++) {
            float a0 = h_s[(r0 + 0) * 128 + kc + k];
            float a1 = h_s[(r0 + 1) * 128 + kc + k];
            float a2 = h_s[(r0 + 2) * 128 + kc + k];
            float a3 = h_s[(r0 + 3) * 128 + kc + k];
            float4 bv = *(const float4*)&w_s[k * 128 + col];
            acc2[0][0] = fmaf(a0, bv.x, acc2[0][0]);
            acc2[0][1] = fmaf(a0, bv.y, acc2[0][1]);
            acc2[0][2] = fmaf(a0, bv.z, acc2[0][2]);
            acc2[0][3] = fmaf(a0, bv.w, acc2[0][3]);
            acc2[1][0] = fmaf(a1, bv.x, acc2[1][0]);
            acc2[1][1] = fmaf(a1, bv.y, acc2[1][1]);
            acc2[1][2] = fmaf(a1, bv.z, acc2[1][2]);
            acc2[1][3] = fmaf(a1, bv.w, acc2[1][3]);
            acc2[2][0] = fmaf(a2, bv.x, acc2[2][0]);
            acc2[2][1] = fmaf(a2, bv.y, acc2[2][1]);
            acc2[2][2] = fmaf(a2, bv.z, acc2[2][2]);
            acc2[2][3] = fmaf(a2, bv.w, acc2[2][3]);
            acc2[3][0] = fmaf(a3, bv.x, acc2[3][0]);
            acc2[3][1] = fmaf(a3, bv.y, acc2[3][1]);
            acc2[3][2] = fmaf(a3, bv.z, acc2[3][2]);
            acc2[3][3] = fmaf(a3, bv.w, acc2[3][3]);
        }
    }

    if (tid < 128) w2_s[tid] = mw2[(size_t)f * NH + tid];
    __syncthreads();

    {
        const float* b1p = mb1 + (size_t)f * NH;
        #pragma unroll
        for (int i = 0; i < 4; i++) {
            float si = 0.0f;
            #pragma unroll
            for (int j = 0; j < 4; j++) {
                float v = fmaxf(acc2[i][j] + b1p[col + j], 0.0f);
                si = fmaf(v, w2_s[col + j], si);
            }
            red_s[(r0 + i) * 33 + cx] = si;
        }
    }
    __syncthreads();

    if (tid < MT) {
        float sum = 0.0f;
        #pragma unroll
        for (int t = 0; t < 32; t++) sum += red_s[tid * 33 + t];
        float zm = smooth_z(z_main[f]);
        atomicAdd(&out[b0 + tid], zm * (sum + mb2[f]));
    }
}

extern "C" void kernel_launch(void* const* d_in, const int* in_sizes, int n_in,
                              void* d_out, int out_size) {
    const int*   mains      = (const int*)  d_in[0];
    const int*   pairs      = (const int*)  d_in[1];
    const float* emb        = (const float*)d_in[2];
    const float* mw0        = (const float*)d_in[3];
    const float* mw1        = (const float*)d_in[4];
    const float* mw2        = (const float*)d_in[5];
    const float* mb0        = (const float*)d_in[6];
    const float* mb1        = (const float*)d_in[7];
    const float* mb2        = (const float*)d_in[8];
    const float* z_main     = (const float*)d_in[9];
    const float* pw0        = (const float*)d_in[10];
    const float* pw1        = (const float*)d_in[11];
    const float* pw2        = (const float*)d_in[12];
    const float* pb0        = (const float*)d_in[13];
    const float* pb1        = (const float*)d_in[14];
    const float* pb2        = (const float*)d_in[15];
    const float* z_pairs    = (const float*)d_in[16];
    const int*   pairs_list = (const int*)  d_in[17];
    const int*   feat_off   = (const int*)  d_in[18];
    float* out = (float*)d_out;

    cudaMemsetAsync(out, 0, NB * sizeof(float), 0);
    main_kernel<<<dim3(NB / MT, NF), 256>>>(mains, emb, mw0, mw1, mw2,
                                            mb0, mb1, mb2, z_main, feat_off, out);
    pair_kernel<<<dim3(NB / MT, NP), 256>>>(pairs, emb, pw0, pw1, pw2,
                                            pb0, pb1, pb2, z_pairs, pairs_list,
                                            feat_off, out);
}

// round 3
// speedup vs baseline: 2.5354x; 2.5354x over previous
#include <cuda_runtime.h>
#include <cstdint>

#define NB 512
#define NF 64
#define NP 2016
#define NE 32
#define NGROUPS (NP + NF)

// SMEM strides in 4B words (stride % 32 == 8 -> conflict-free quad patterns)
#define SE 72    // E  [128][72]   (K0 <= 64)
#define SW 136   // W0 [64][136], W1 [128][136]
#define SH 136   // H  [128][136]

// SMEM byte offsets
#define OFF_W1 0
#define OFF_W0 69632
#define OFF_E  104448
#define OFF_H  141312
#define OFF_B0 210944
#define OFF_B1 211456
#define OFF_W2 211968
#define SMEM_TOTAL 212480

__device__ __forceinline__ uint32_t f2tf32(float x) {
    uint32_t r;
    asm("cvt.rna.tf32.f32 %0, %1;" : "=r"(r) : "f"(x));
    return r;
}

#define MMA_TF32(d, a, b0v, b1v)                                               \
    asm volatile("mma.sync.aligned.m16n8k8.row.col.f32.tf32.tf32.f32 "         \
                 "{%0,%1,%2,%3}, {%4,%5,%6,%7}, {%8,%9}, {%0,%1,%2,%3};"       \
                 : "+f"((d)[0]), "+f"((d)[1]), "+f"((d)[2]), "+f"((d)[3])      \
                 : "r"((a)[0]), "r"((a)[1]), "r"((a)[2]), "r"((a)[3]),         \
                   "r"(b0v), "r"(b1v))

__device__ __forceinline__ float smooth_z(float z) {
    float s = fmaf(-2.0f * z * z, z, fmaf(1.5f, z, 0.5f));
    s = (z <= -0.5f) ? 0.0f : s;
    s = (z >=  0.5f) ? 1.0f : s;
    return s;
}

extern __shared__ char smem_raw[];

__global__ __launch_bounds__(256, 1)
void dnamite_mma_kernel(const int*   __restrict__ mains,
                        const int*   __restrict__ pairs,
                        const float* __restrict__ emb,
                        const float* __restrict__ mw0, const float* __restrict__ mw1,
                        const float* __restrict__ mw2, const float* __restrict__ mb0,
                        const float* __restrict__ mb1, const float* __restrict__ mb2,
                        const float* __restrict__ z_main,
                        const float* __restrict__ pw0, const float* __restrict__ pw1,
                        const float* __restrict__ pw2, const float* __restrict__ pb0,
                        const float* __restrict__ pb1, const float* __restrict__ pb2,
                        const float* __restrict__ z_pairs,
                        const int*   __restrict__ pairs_list,
                        const int*   __restrict__ feat_off,
                        float*       __restrict__ out)
{
    uint32_t* W1s = (uint32_t*)(smem_raw + OFF_W1);
    uint32_t* W0s = (uint32_t*)(smem_raw + OFF_W0);
    uint32_t* Es  = (uint32_t*)(smem_raw + OFF_E);
    uint32_t* Hs  = (uint32_t*)(smem_raw + OFF_H);
    float*    b0s = (float*)(smem_raw + OFF_B0);
    float*    b1s = (float*)(smem_raw + OFF_B1);
    float*    w2s = (float*)(smem_raw + OFF_W2);

    const int tid  = threadIdx.x;
    const int g    = blockIdx.x;
    const bool is_pair = (g < NP);

    const int lane = tid & 31;
    const int qr   = lane >> 2;   // 0..7
    const int qc   = lane & 3;    // 0..3
    const int w    = tid >> 5;    // warp 0..7
    const int mq   = w >> 1;      // 0..3 : rows [mq*32, mq*32+32)
    const int nh   = w & 1;       // 0..1 : cols [nh*64, nh*64+64)

    const float *w0g, *w1g, *b0g, *b1g, *w2g;
    float b2v, zv;
    int offi = 0, offj = 0, K0, f_ = 0;
    if (is_pair) {
        K0  = 64;
        w0g = pw0 + (size_t)g * 64 * 128;
        w1g = pw1 + (size_t)g * 128 * 128;
        w2g = pw2 + (size_t)g * 128;
        b0g = pb0 + (size_t)g * 128;
        b1g = pb1 + (size_t)g * 128;
        b2v = pb2[g];
        zv  = smooth_z(z_pairs[g]);
        offi = feat_off[pairs_list[2 * g + 0]];
        offj = feat_off[pairs_list[2 * g + 1]];
    } else {
        f_  = g - NP;
        K0  = 32;
        w0g = mw0 + (size_t)f_ * 32 * 128;
        w1g = mw1 + (size_t)f_ * 128 * 128;
        w2g = mw2 + (size_t)f_ * 128;
        b0g = mb0 + (size_t)f_ * 128;
        b1g = mb1 + (size_t)f_ * 128;
        b2v = mb2[f_];
        zv  = smooth_z(z_main[f_]);
    }
    const int ks0 = K0 >> 3;

    // ---- weights -> SMEM (tf32 bits), biases/w2 -> SMEM (f32) ----
    for (int i = tid; i < K0 * 128; i += 256) {
        int k = i >> 7, n = i & 127;
        W0s[k * SW + n] = f2tf32(w0g[i]);
    }
    for (int i = tid; i < 128 * 128; i += 256) {
        int k = i >> 7, n = i & 127;
        W1s[k * SW + n] = f2tf32(w1g[i]);
    }
    if (tid < 128) {
        b0s[tid] = b0g[tid];
        b1s[tid] = b1g[tid];
        w2s[tid] = w2g[tid];
    }
    __syncthreads();

    #pragma unroll 1
    for (int mt = 0; mt < 4; mt++) {
        const int Mbase = mt * 128;

        // ---- gather E[128][K0] (tf32 bits) ----
        {
            const int r = tid >> 1, half = tid & 1;
            if (is_pair || half == 0) {
                int bin, off;
                if (is_pair) {
                    bin = pairs[(((size_t)(Mbase + r)) * NP + g) * 2 + half];
                    off = half ? offj : offi;
                } else {
                    bin = mains[(size_t)(Mbase + r) * NF + f_];
                    off = feat_off[f_];
                }
                const float4* src = (const float4*)(emb + (size_t)(off + bin) * NE);
                uint32_t* dst = Es + r * SE + half * 32;
                #pragma unroll
                for (int q = 0; q < 8; q++) {
                    float4 t = src[q];
                    dst[4 * q + 0] = f2tf32(t.x);
                    dst[4 * q + 1] = f2tf32(t.y);
                    dst[4 * q + 2] = f2tf32(t.z);
                    dst[4 * q + 3] = f2tf32(t.w);
                }
            }
        }
        __syncthreads();

        // ---- layer 0: H = relu(E @ W0 + b0) ----
        float acc[2][8][4];
        #pragma unroll
        for (int s = 0; s < 2; s++)
            #pragma unroll
            for (int n = 0; n < 8; n++)
                #pragma unroll
                for (int j = 0; j < 4; j++) acc[s][n][j] = 0.0f;

        const int ra = mq * 32 + qr;
        #pragma unroll
        for (int ks = 0; ks < 8; ks++) {
            if (ks >= ks0) break;
            uint32_t a[2][4];
            const int c = ks * 8 + qc;
            #pragma unroll
            for (int s = 0; s < 2; s++) {
                const uint32_t* e = Es + (ra + 16 * s) * SE + c;
                a[s][0] = e[0];
                a[s][1] = e[8 * SE];
                a[s][2] = e[4];
                a[s][3] = e[8 * SE + 4];
            }
            const uint32_t* wrow = W0s + (ks * 8 + qc) * SW + nh * 64 + qr;
            #pragma unroll
            for (int n = 0; n < 8; n++) {
                uint32_t bv0 = wrow[n * 8];
                uint32_t bv1 = wrow[4 * SW + n * 8];
                MMA_TF32(acc[0][n], a[0], bv0, bv1);
                MMA_TF32(acc[1][n], a[1], bv0, bv1);
            }
        }

        // epilogue0: relu+bias -> Hs (tf32 bits)
        #pragma unroll
        for (int s = 0; s < 2; s++)
            #pragma unroll
            for (int n = 0; n < 8; n++) {
                int row = mq * 32 + 16 * s + qr;
                int col = nh * 64 + n * 8 + 2 * qc;
                uint2 v01, v23;
                v01.x = f2tf32(fmaxf(acc[s][n][0] + b0s[col],     0.0f));
                v01.y = f2tf32(fmaxf(acc[s][n][1] + b0s[col + 1], 0.0f));
                v23.x = f2tf32(fmaxf(acc[s][n][2] + b0s[col],     0.0f));
                v23.y = f2tf32(fmaxf(acc[s][n][3] + b0s[col + 1], 0.0f));
                *(uint2*)&Hs[row * SH + col]       = v01;
                *(uint2*)&Hs[(row + 8) * SH + col] = v23;
            }
        __syncthreads();

        // ---- layer 1: D1 = H @ W1 ----
        #pragma unroll
        for (int s = 0; s < 2; s++)
            #pragma unroll
            for (int n = 0; n < 8; n++)
                #pragma unroll
                for (int j = 0; j < 4; j++) acc[s][n][j] = 0.0f;

        #pragma unroll
        for (int ks = 0; ks < 16; ks++) {
            uint32_t a[2][4];
            const int c = ks * 8 + qc;
            #pragma unroll
            for (int s = 0; s < 2; s++) {
                const uint32_t* h = Hs + (ra + 16 * s) * SH + c;
                a[s][0] = h[0];
                a[s][1] = h[8 * SH];
                a[s][2] = h[4];
                a[s][3] = h[8 * SH + 4];
            }
            const uint32_t* wrow = W1s + (ks * 8 + qc) * SW + nh * 64 + qr;
            #pragma unroll
            for (int n = 0; n < 8; n++) {
                uint32_t bv0 = wrow[n * 8];
                uint32_t bv1 = wrow[4 * SW + n * 8];
                MMA_TF32(acc[0][n], a[0], bv0, bv1);
                MMA_TF32(acc[1][n], a[1], bv0, bv1);
            }
        }

        // ---- epilogue1: relu+bias, dot w2, quad-reduce, atomic ----
        float rs[4] = {0.0f, 0.0f, 0.0f, 0.0f};
        #pragma unroll
        for (int s = 0; s < 2; s++)
            #pragma unroll
            for (int n = 0; n < 8; n++) {
                int col = nh * 64 + n * 8 + 2 * qc;
                float ba = b1s[col], bb = b1s[col + 1];
                float wa = w2s[col], wb = w2s[col + 1];
                rs[s * 2 + 0] += fmaxf(acc[s][n][0] + ba, 0.0f) * wa
                               + fmaxf(acc[s][n][1] + bb, 0.0f) * wb;
                rs[s * 2 + 1] += fmaxf(acc[s][n][2] + ba, 0.0f) * wa
                               + fmaxf(acc[s][n][3] + bb, 0.0f) * wb;
            }
        #pragma unroll
        for (int i = 0; i < 4; i++) {
            rs[i] += __shfl_xor_sync(0xFFFFFFFF, rs[i], 1);
            rs[i] += __shfl_xor_sync(0xFFFFFFFF, rs[i], 2);
        }
        if (qc == 0) {
            #pragma unroll
            for (int i = 0; i < 4; i++) {
                int row = Mbase + mq * 32 + 16 * (i >> 1) + 8 * (i & 1) + qr;
                float v = rs[i] + (nh == 0 ? b2v : 0.0f);
                atomicAdd(&out[row], zv * v);
            }
        }
        __syncthreads();  // protect Es/Hs before next tile
    }
}

extern "C" void kernel_launch(void* const* d_in, const int* in_sizes, int n_in,
                              void* d_out, int out_size) {
    const int*   mains      = (const int*)  d_in[0];
    const int*   pairs      = (const int*)  d_in[1];
    const float* emb        = (const float*)d_in[2];
    const float* mw0        = (const float*)d_in[3];
    const float* mw1        = (const float*)d_in[4];
    const float* mw2        = (const float*)d_in[5];
    const float* mb0        = (const float*)d_in[6];
    const float* mb1        = (const float*)d_in[7];
    const float* mb2        = (const float*)d_in[8];
    const float* z_main     = (const float*)d_in[9];
    const float* pw0        = (const float*)d_in[10];
    const float* pw1        = (const float*)d_in[11];
    const float* pw2        = (const float*)d_in[12];
    const float* pb0        = (const float*)d_in[13];
    const float* pb1        = (const float*)d_in[14];
    const float* pb2        = (const float*)d_in[15];
    const float* z_pairs    = (const float*)d_in[16];
    const int*   pairs_list = (const int*)  d_in[17];
    const int*   feat_off   = (const int*)  d_in[18];
    float* out = (float*)d_out;

    static int configured = 0;
    if (!configured) {
        cudaFuncSetAttribute(dnamite_mma_kernel,
                             cudaFuncAttributeMaxDynamicSharedMemorySize, SMEM_TOTAL);
        configured = 1;
    }
    cudaMemsetAsync(out, 0, NB * sizeof(float), 0);
    dnamite_mma_kernel<<<NGROUPS, 256, SMEM_TOTAL>>>(
        mains, pairs, emb, mw0, mw1, mw2, mb0, mb1, mb2, z_main,
        pw0, pw1, pw2, pb0, pb1, pb2, z_pairs, pairs_list, feat_off, out);
}

// round 4
// speedup vs baseline: 5.3630x; 2.1153x over previous
#include <cuda_runtime.h>
#include <cuda_fp16.h>
#include <cstdint>

#define NB 512
#define NF 64
#define NP 2016
#define NE 32
#define NGROUPS (NP + NF)

// strides in 4B words (stride % 32 == 4 -> conflict-free fragment patterns)
#define SE  36   // E  [128 rows][32 h2-words + 4 pad]
#define SW0 36   // W0^T [128 n][32 kp-words + 4 pad]
#define SW1 68   // W1^T [128 n][64 kp-words + 4 pad]

// SMEM byte offsets
#define OFF_WT1 0        // 128*68*4 = 34816
#define OFF_WT0 34816    // 128*36*4 = 18432
#define OFF_E   53248    // 128*36*4 = 18432
#define OFF_B0  71680
#define OFF_B1  72192
#define OFF_W2  72704
#define SMEM_TOTAL 73216

__device__ __forceinline__ uint32_t pack_h2(float lo, float hi) {
    uint32_t d;
    asm("cvt.rn.f16x2.f32 %0, %1, %2;" : "=r"(d) : "f"(hi), "f"(lo));
    return d;
}

#define MMA_F16(d, a0, a1, a2, a3, bv0, bv1)                                   \
    asm volatile("mma.sync.aligned.m16n8k16.row.col.f32.f16.f16.f32 "          \
                 "{%0,%1,%2,%3}, {%4,%5,%6,%7}, {%8,%9}, {%0,%1,%2,%3};"       \
                 : "+f"((d)[0]), "+f"((d)[1]), "+f"((d)[2]), "+f"((d)[3])      \
                 : "r"(a0), "r"(a1), "r"(a2), "r"(a3), "r"(bv0), "r"(bv1))

__device__ __forceinline__ float smooth_z(float z) {
    float s = fmaf(-2.0f * z * z, z, fmaf(1.5f, z, 0.5f));
    s = (z <= -0.5f) ? 0.0f : s;
    s = (z >=  0.5f) ? 1.0f : s;
    return s;
}

extern __shared__ char smem_raw[];

__global__ __launch_bounds__(256, 2)
void dnamite_h16_kernel(const int*   __restrict__ mains,
                        const int*   __restrict__ pairs,
                        const float* __restrict__ emb,
                        const float* __restrict__ mw0, const float* __restrict__ mw1,
                        const float* __restrict__ mw2, const float* __restrict__ mb0,
                        const float* __restrict__ mb1, const float* __restrict__ mb2,
                        const float* __restrict__ z_main,
                        const float* __restrict__ pw0, const float* __restrict__ pw1,
                        const float* __restrict__ pw2, const float* __restrict__ pb0,
                        const float* __restrict__ pb1, const float* __restrict__ pb2,
                        const float* __restrict__ z_pairs,
                        const int*   __restrict__ pairs_list,
                        const int*   __restrict__ feat_off,
                        float*       __restrict__ out)
{
    uint32_t* WT1s = (uint32_t*)(smem_raw + OFF_WT1);
    uint32_t* WT0s = (uint32_t*)(smem_raw + OFF_WT0);
    uint32_t* E2   = (uint32_t*)(smem_raw + OFF_E);
    float*    b0s  = (float*)(smem_raw + OFF_B0);
    float*    b1s  = (float*)(smem_raw + OFF_B1);
    float*    w2s  = (float*)(smem_raw + OFF_W2);

    const int tid  = threadIdx.x;
    const int g    = blockIdx.x;
    const bool is_pair = (g < NP);

    const int lane = tid & 31;
    const int qr   = lane >> 2;   // 0..7
    const int qc   = lane & 3;    // 0..3
    const int w    = tid >> 5;    // warp 0..7 -> rows [w*16, w*16+16)

    const float *w0g, *w1g, *b0g, *b1g, *w2g;
    float b2v, zv;
    int offi = 0, offj = 0, K0, f_ = 0;
    if (is_pair) {
        K0  = 64;
        w0g = pw0 + (size_t)g * 64 * 128;
        w1g = pw1 + (size_t)g * 128 * 128;
        w2g = pw2 + (size_t)g * 128;
        b0g = pb0 + (size_t)g * 128;
        b1g = pb1 + (size_t)g * 128;
        b2v = pb2[g];
        zv  = smooth_z(z_pairs[g]);
        offi = feat_off[pairs_list[2 * g + 0]];
        offj = feat_off[pairs_list[2 * g + 1]];
    } else {
        f_  = g - NP;
        K0  = 32;
        w0g = mw0 + (size_t)f_ * 32 * 128;
        w1g = mw1 + (size_t)f_ * 128 * 128;
        w2g = mw2 + (size_t)f_ * 128;
        b0g = mb0 + (size_t)f_ * 128;
        b1g = mb1 + (size_t)f_ * 128;
        b2v = mb2[f_];
        zv  = smooth_z(z_main[f_]);
        offi = feat_off[f_];
    }

    // ---- weights -> SMEM as W^T [n][k-pair] in f16x2 ----
    for (int i = tid; i < 128 * (K0 >> 1); i += 256) {
        int n = i & 127, kp = i >> 7;
        float v0 = w0g[(2 * kp + 0) * 128 + n];
        float v1 = w0g[(2 * kp + 1) * 128 + n];
        WT0s[n * SW0 + kp] = pack_h2(v0, v1);
    }
    if (!is_pair) {  // zero-pad W0^T k-words 16..31 so unified K=64 path is safe
        for (int i = tid; i < 128 * 16; i += 256) {
            int n = i & 127, kp = i >> 7;
            WT0s[n * SW0 + 16 + kp] = 0u;
        }
    }
    for (int i = tid; i < 128 * 64; i += 256) {
        int n = i & 127, kp = i >> 7;
        float v0 = w1g[(2 * kp + 0) * 128 + n];
        float v1 = w1g[(2 * kp + 1) * 128 + n];
        WT1s[n * SW1 + kp] = pack_h2(v0, v1);
    }
    if (tid < 128) {
        b0s[tid] = b0g[tid];
        b1s[tid] = b1g[tid];
        w2s[tid] = w2g[tid];
    }

    #pragma unroll 1
    for (int mt = 0; mt < 4; mt++) {
        const int Mbase = mt * 128;

        // ---- gather E[128][64 h] as f16x2 words (pairs: concat; mains: pad 0) ----
        {
            const int r = tid >> 1, side = tid & 1;
            uint32_t* dst = E2 + r * SE + side * 16;
            if (is_pair || side == 0) {
                int bin, off;
                if (is_pair) {
                    bin = pairs[(((size_t)(Mbase + r)) * NP + g) * 2 + side];
                    off = side ? offj : offi;
                } else {
                    bin = mains[(size_t)(Mbase + r) * NF + f_];
                    off = offi;
                }
                const float4* src = (const float4*)(emb + (size_t)(off + bin) * NE);
                #pragma unroll
                for (int q = 0; q < 4; q++) {
                    float4 t0 = src[2 * q], t1 = src[2 * q + 1];
                    uint4 v;
                    v.x = pack_h2(t0.x, t0.y);
                    v.y = pack_h2(t0.z, t0.w);
                    v.z = pack_h2(t1.x, t1.y);
                    v.w = pack_h2(t1.z, t1.w);
                    *(uint4*)(dst + 4 * q) = v;
                }
            } else {  // mains, side==1: zero upper half
                uint4 z = {0u, 0u, 0u, 0u};
                #pragma unroll
                for (int q = 0; q < 4; q++) *(uint4*)(dst + 4 * q) = z;
            }
        }
        __syncthreads();

        // ---- layer 0 A fragments (all 4 k16-steps) ----
        const uint32_t* er0 = E2 + (w * 16 + qr) * SE + qc;
        const uint32_t* er1 = er0 + 8 * SE;
        uint32_t A0[4][4];
        #pragma unroll
        for (int ks = 0; ks < 4; ks++) {
            A0[ks][0] = er0[ks * 8];
            A0[ks][1] = er1[ks * 8];
            A0[ks][2] = er0[ks * 8 + 4];
            A0[ks][3] = er1[ks * 8 + 4];
        }

        // ---- layer 0: H (registers, packed f16x2) ----
        uint32_t Hp0[16], Hp1[16];
        #pragma unroll
        for (int half = 0; half < 2; half++) {
            float acc[8][4];
            #pragma unroll
            for (int t = 0; t < 8; t++)
                #pragma unroll
                for (int j = 0; j < 4; j++) acc[t][j] = 0.0f;

            const uint32_t* wb = WT0s + (half * 64 + qr) * SW0 + qc;
            #pragma unroll
            for (int ks = 0; ks < 4; ks++) {
                #pragma unroll
                for (int t = 0; t < 8; t++) {
                    uint32_t bv0 = wb[t * 8 * SW0 + ks * 8];
                    uint32_t bv1 = wb[t * 8 * SW0 + ks * 8 + 4];
                    MMA_F16(acc[t], A0[ks][0], A0[ks][1], A0[ks][2], A0[ks][3], bv0, bv1);
                }
            }
            #pragma unroll
            for (int t = 0; t < 8; t++) {
                int tt  = half * 8 + t;
                int col = tt * 8 + 2 * qc;
                float ba = b0s[col], bb = b0s[col + 1];
                Hp0[tt] = pack_h2(fmaxf(acc[t][0] + ba, 0.0f), fmaxf(acc[t][1] + bb, 0.0f));
                Hp1[tt] = pack_h2(fmaxf(acc[t][2] + ba, 0.0f), fmaxf(acc[t][3] + bb, 0.0f));
            }
        }

        // ---- layer 1 (A from registers) + fused relu/bias/w2-dot ----
        float s0 = 0.0f, s1 = 0.0f;
        #pragma unroll
        for (int half = 0; half < 2; half++) {
            float acc[8][4];
            #pragma unroll
            for (int t = 0; t < 8; t++)
                #pragma unroll
                for (int j = 0; j < 4; j++) acc[t][j] = 0.0f;

            const uint32_t* wb = WT1s + (half * 64 + qr) * SW1 + qc;
            #pragma unroll
            for (int K = 0; K < 8; K++) {
                uint32_t a0 = Hp0[2 * K],     a1 = Hp1[2 * K];
                uint32_t a2 = Hp0[2 * K + 1], a3 = Hp1[2 * K + 1];
                #pragma unroll
                for (int t = 0; t < 8; t++) {
                    uint32_t bv0 = wb[t * 8 * SW1 + K * 8];
                    uint32_t bv1 = wb[t * 8 * SW1 + K * 8 + 4];
                    MMA_F16(acc[t], a0, a1, a2, a3, bv0, bv1);
                }
            }
            #pragma unroll
            for (int t = 0; t < 8; t++) {
                int col = (half * 8 + t) * 8 + 2 * qc;
                float ba = b1s[col], bb = b1s[col + 1];
                float wa = w2s[col], wb2 = w2s[col + 1];
                s0 += fmaxf(acc[t][0] + ba, 0.0f) * wa + fmaxf(acc[t][1] + bb, 0.0f) * wb2;
                s1 += fmaxf(acc[t][2] + ba, 0.0f) * wa + fmaxf(acc[t][3] + bb, 0.0f) * wb2;
            }
        }

        // quad-reduce over qc and accumulate
        s0 += __shfl_xor_sync(0xFFFFFFFF, s0, 1);
        s0 += __shfl_xor_sync(0xFFFFFFFF, s0, 2);
        s1 += __shfl_xor_sync(0xFFFFFFFF, s1, 1);
        s1 += __shfl_xor_sync(0xFFFFFFFF, s1, 2);
        if (qc == 0) {
            int row = Mbase + w * 16 + qr;
            atomicAdd(&out[row],     zv * (s0 + b2v));
            atomicAdd(&out[row + 8], zv * (s1 + b2v));
        }
        __syncthreads();  // protect E before next tile's gather
    }
}

extern "C" void kernel_launch(void* const* d_in, const int* in_sizes, int n_in,
                              void* d_out, int out_size) {
    const int*   mains      = (const int*)  d_in[0];
    const int*   pairs      = (const int*)  d_in[1];
    const float* emb        = (const float*)d_in[2];
    const float* mw0        = (const float*)d_in[3];
    const float* mw1        = (const float*)d_in[4];
    const float* mw2        = (const float*)d_in[5];
    const float* mb0        = (const float*)d_in[6];
    const float* mb1        = (const float*)d_in[7];
    const float* mb2        = (const float*)d_in[8];
    const float* z_main     = (const float*)d_in[9];
    const float* pw0        = (const float*)d_in[10];
    const float* pw1        = (const float*)d_in[11];
    const float* pw2        = (const float*)d_in[12];
    const float* pb0        = (const float*)d_in[13];
    const float* pb1        = (const float*)d_in[14];
    const float* pb2        = (const float*)d_in[15];
    const float* z_pairs    = (const float*)d_in[16];
    const int*   pairs_list = (const int*)  d_in[17];
    const int*   feat_off   = (const int*)  d_in[18];
    float* out = (float*)d_out;

    static int configured = 0;
    if (!configured) {
        cudaFuncSetAttribute(dnamite_h16_kernel,
                             cudaFuncAttributeMaxDynamicSharedMemorySize, SMEM_TOTAL);
        configured = 1;
    }
    cudaMemsetAsync(out, 0, NB * sizeof(float), 0);
    dnamite_h16_kernel<<<NGROUPS, 256, SMEM_TOTAL>>>(
        mains, pairs, emb, mw0, mw1, mw2, mb0, mb1, mb2, z_main,
        pw0, pw1, pw2, pb0, pb1, pb2, z_pairs, pairs_list, feat_off, out);
}

// round 5
// speedup vs baseline: 5.3796x; 1.0031x over previous
#include <cuda_runtime.h>
#include <cuda_fp16.h>
#include <cstdint>

#define NB 512
#define NF 64
#define NP 2016
#define NE 32
#define NGROUPS (NP + NF)

// strides in 4B words (stride % 32 == 4 -> conflict-free fragment patterns)
#define SE  36   // E  [128 rows][32 h2-words + 4 pad]
#define SW0 36   // W0^T [128 n][32 kp-words + 4 pad]
#define SW1 68   // W1^T [128 n][64 kp-words + 4 pad]

// SMEM byte offsets
#define OFF_WT1 0        // 128*68*4 = 34816
#define OFF_WT0 34816    // 128*36*4 = 18432
#define OFF_E   53248    // 128*36*4 = 18432
#define OFF_B0  71680
#define OFF_B1  72192
#define OFF_W2  72704
#define SMEM_TOTAL 73216

__device__ __forceinline__ uint32_t pack_h2(float lo, float hi) {
    uint32_t d;
    asm("cvt.rn.f16x2.f32 %0, %1, %2;" : "=r"(d) : "f"(hi), "f"(lo));
    return d;
}

#define MMA_F16(d, a0, a1, a2, a3, bv0, bv1)                                   \
    asm volatile("mma.sync.aligned.m16n8k16.row.col.f32.f16.f16.f32 "          \
                 "{%0,%1,%2,%3}, {%4,%5,%6,%7}, {%8,%9}, {%0,%1,%2,%3};"       \
                 : "+f"((d)[0]), "+f"((d)[1]), "+f"((d)[2]), "+f"((d)[3])      \
                 : "r"(a0), "r"(a1), "r"(a2), "r"(a3), "r"(bv0), "r"(bv1))

__device__ __forceinline__ float smooth_z(float z) {
    float s = fmaf(-2.0f * z * z, z, fmaf(1.5f, z, 0.5f));
    s = (z <= -0.5f) ? 0.0f : s;
    s = (z >=  0.5f) ? 1.0f : s;
    return s;
}

extern __shared__ char smem_raw[];

__global__ __launch_bounds__(128, 2)
void dnamite_h16_kernel(const int*   __restrict__ mains,
                        const int*   __restrict__ pairs,
                        const float* __restrict__ emb,
                        const float* __restrict__ mw0, const float* __restrict__ mw1,
                        const float* __restrict__ mw2, const float* __restrict__ mb0,
                        const float* __restrict__ mb1, const float* __restrict__ mb2,
                        const float* __restrict__ z_main,
                        const float* __restrict__ pw0, const float* __restrict__ pw1,
                        const float* __restrict__ pw2, const float* __restrict__ pb0,
                        const float* __restrict__ pb1, const float* __restrict__ pb2,
                        const float* __restrict__ z_pairs,
                        const int*   __restrict__ pairs_list,
                        const int*   __restrict__ feat_off,
                        float*       __restrict__ out)
{
    uint32_t* WT1s = (uint32_t*)(smem_raw + OFF_WT1);
    uint32_t* WT0s = (uint32_t*)(smem_raw + OFF_WT0);
    uint32_t* E2   = (uint32_t*)(smem_raw + OFF_E);
    float*    b0s  = (float*)(smem_raw + OFF_B0);
    float*    b1s  = (float*)(smem_raw + OFF_B1);
    float*    w2s  = (float*)(smem_raw + OFF_W2);

    const int tid  = threadIdx.x;
    const int g    = blockIdx.x;
    const bool is_pair = (g < NP);

    const int lane = tid & 31;
    const int qr   = lane >> 2;   // 0..7
    const int qc   = lane & 3;    // 0..3
    const int w    = tid >> 5;    // warp 0..3 -> rows [w*32, w*32+32)

    const float *w0g, *w1g, *b0g, *b1g, *w2g;
    float b2v, zv;
    int offi = 0, offj = 0, K0, f_ = 0;
    if (is_pair) {
        K0  = 64;
        w0g = pw0 + (size_t)g * 64 * 128;
        w1g = pw1 + (size_t)g * 128 * 128;
        w2g = pw2 + (size_t)g * 128;
        b0g = pb0 + (size_t)g * 128;
        b1g = pb1 + (size_t)g * 128;
        b2v = pb2[g];
        zv  = smooth_z(z_pairs[g]);
        offi = feat_off[pairs_list[2 * g + 0]];
        offj = feat_off[pairs_list[2 * g + 1]];
    } else {
        f_  = g - NP;
        K0  = 32;
        w0g = mw0 + (size_t)f_ * 32 * 128;
        w1g = mw1 + (size_t)f_ * 128 * 128;
        w2g = mw2 + (size_t)f_ * 128;
        b0g = mb0 + (size_t)f_ * 128;
        b1g = mb1 + (size_t)f_ * 128;
        b2v = mb2[f_];
        zv  = smooth_z(z_main[f_]);
        offi = feat_off[f_];
    }

    // ---- weights -> SMEM as W^T [n][k-pair] in f16x2 ----
    for (int i = tid; i < 128 * (K0 >> 1); i += 128) {
        int n = i & 127, kp = i >> 7;
        float v0 = w0g[(2 * kp + 0) * 128 + n];
        float v1 = w0g[(2 * kp + 1) * 128 + n];
        WT0s[n * SW0 + kp] = pack_h2(v0, v1);
    }
    if (!is_pair) {  // zero-pad W0^T k-words 16..31 so unified K=64 path is safe
        for (int i = tid; i < 128 * 16; i += 128) {
            int n = i & 127, kp = i >> 7;
            WT0s[n * SW0 + 16 + kp] = 0u;
        }
    }
    for (int i = tid; i < 128 * 64; i += 128) {
        int n = i & 127, kp = i >> 7;
        float v0 = w1g[(2 * kp + 0) * 128 + n];
        float v1 = w1g[(2 * kp + 1) * 128 + n];
        WT1s[n * SW1 + kp] = pack_h2(v0, v1);
    }
    if (tid < 128) {
        b0s[tid] = b0g[tid];
        b1s[tid] = b1g[tid];
        w2s[tid] = w2g[tid];
    }

    #pragma unroll 1
    for (int mt = 0; mt < 4; mt++) {
        const int Mbase = mt * 128;

        // ---- gather E[128][64 h] as f16x2 words (pairs: concat; mains: pad 0) ----
        #pragma unroll
        for (int rr = tid; rr < 256; rr += 128) {
            const int r = rr >> 1, side = rr & 1;
            uint32_t* dst = E2 + r * SE + side * 16;
            if (is_pair || side == 0) {
                int bin, off;
                if (is_pair) {
                    bin = pairs[(((size_t)(Mbase + r)) * NP + g) * 2 + side];
                    off = side ? offj : offi;
                } else {
                    bin = mains[(size_t)(Mbase + r) * NF + f_];
                    off = offi;
                }
                const float4* src = (const float4*)(emb + (size_t)(off + bin) * NE);
                #pragma unroll
                for (int q = 0; q < 4; q++) {
                    float4 t0 = src[2 * q], t1 = src[2 * q + 1];
                    uint4 v;
                    v.x = pack_h2(t0.x, t0.y);
                    v.y = pack_h2(t0.z, t0.w);
                    v.z = pack_h2(t1.x, t1.y);
                    v.w = pack_h2(t1.z, t1.w);
                    *(uint4*)(dst + 4 * q) = v;
                }
            } else {  // mains, side==1: zero upper half
                uint4 z = {0u, 0u, 0u, 0u};
                #pragma unroll
                for (int q = 0; q < 4; q++) *(uint4*)(dst + 4 * q) = z;
            }
        }
        __syncthreads();

        // ---- layer 0 A fragments (2 m-subtiles x 4 k16-steps) ----
        uint32_t A0[2][4][4];
        #pragma unroll
        for (int m = 0; m < 2; m++) {
            const uint32_t* er0 = E2 + (w * 32 + m * 16 + qr) * SE + qc;
            const uint32_t* er1 = er0 + 8 * SE;
            #pragma unroll
            for (int ks = 0; ks < 4; ks++) {
                A0[m][ks][0] = er0[ks * 8];
                A0[m][ks][1] = er1[ks * 8];
                A0[m][ks][2] = er0[ks * 8 + 4];
                A0[m][ks][3] = er1[ks * 8 + 4];
            }
        }

        // ---- layer 0: H (registers, packed f16x2) ----
        uint32_t Hp0[2][16], Hp1[2][16];
        #pragma unroll
        for (int half = 0; half < 2; half++) {
            float acc[2][8][4];
            #pragma unroll
            for (int m = 0; m < 2; m++)
                #pragma unroll
                for (int t = 0; t < 8; t++)
                    #pragma unroll
                    for (int j = 0; j < 4; j++) acc[m][t][j] = 0.0f;

            const uint32_t* wb = WT0s + (half * 64 + qr) * SW0 + qc;
            #pragma unroll
            for (int ks = 0; ks < 4; ks++) {
                #pragma unroll
                for (int t = 0; t < 8; t++) {
                    uint32_t bv0 = wb[t * 8 * SW0 + ks * 8];
                    uint32_t bv1 = wb[t * 8 * SW0 + ks * 8 + 4];
                    MMA_F16(acc[0][t], A0[0][ks][0], A0[0][ks][1], A0[0][ks][2], A0[0][ks][3], bv0, bv1);
                    MMA_F16(acc[1][t], A0[1][ks][0], A0[1][ks][1], A0[1][ks][2], A0[1][ks][3], bv0, bv1);
                }
            }
            #pragma unroll
            for (int t = 0; t < 8; t++) {
                int tt  = half * 8 + t;
                int col = tt * 8 + 2 * qc;
                float ba = b0s[col], bb = b0s[col + 1];
                #pragma unroll
                for (int m = 0; m < 2; m++) {
                    Hp0[m][tt] = pack_h2(fmaxf(acc[m][t][0] + ba, 0.0f), fmaxf(acc[m][t][1] + bb, 0.0f));
                    Hp1[m][tt] = pack_h2(fmaxf(acc[m][t][2] + ba, 0.0f), fmaxf(acc[m][t][3] + bb, 0.0f));
                }
            }
        }

        // ---- layer 1 (A from registers) + fused relu/bias/w2-dot ----
        float s0[2] = {0.0f, 0.0f}, s1[2] = {0.0f, 0.0f};
        #pragma unroll
        for (int half = 0; half < 2; half++) {
            float acc[2][8][4];
            #pragma unroll
            for (int m = 0; m < 2; m++)
                #pragma unroll
                for (int t = 0; t < 8; t++)
                    #pragma unroll
                    for (int j = 0; j < 4; j++) acc[m][t][j] = 0.0f;

            const uint32_t* wb = WT1s + (half * 64 + qr) * SW1 + qc;
            #pragma unroll
            for (int K = 0; K < 8; K++) {
                #pragma unroll
                for (int t = 0; t < 8; t++) {
                    uint32_t bv0 = wb[t * 8 * SW1 + K * 8];
                    uint32_t bv1 = wb[t * 8 * SW1 + K * 8 + 4];
                    MMA_F16(acc[0][t], Hp0[0][2 * K], Hp1[0][2 * K], Hp0[0][2 * K + 1], Hp1[0][2 * K + 1], bv0, bv1);
                    MMA_F16(acc[1][t], Hp0[1][2 * K], Hp1[1][2 * K], Hp0[1][2 * K + 1], Hp1[1][2 * K + 1], bv0, bv1);
                }
            }
            #pragma unroll
            for (int t = 0; t < 8; t++) {
                int col = (half * 8 + t) * 8 + 2 * qc;
                float ba = b1s[col], bb = b1s[col + 1];
                float wa = w2s[col], wb2 = w2s[col + 1];
                #pragma unroll
                for (int m = 0; m < 2; m++) {
                    s0[m] += fmaxf(acc[m][t][0] + ba, 0.0f) * wa + fmaxf(acc[m][t][1] + bb, 0.0f) * wb2;
                    s1[m] += fmaxf(acc[m][t][2] + ba, 0.0f) * wa + fmaxf(acc[m][t][3] + bb, 0.0f) * wb2;
                }
            }
        }

        // quad-reduce over qc and accumulate
        #pragma unroll
        for (int m = 0; m < 2; m++) {
            s0[m] += __shfl_xor_sync(0xFFFFFFFF, s0[m], 1);
            s0[m] += __shfl_xor_sync(0xFFFFFFFF, s0[m], 2);
            s1[m] += __shfl_xor_sync(0xFFFFFFFF, s1[m], 1);
            s1[m] += __shfl_xor_sync(0xFFFFFFFF, s1[m], 2);
        }
        if (qc == 0) {
            #pragma unroll
            for (int m = 0; m < 2; m++) {
                int row = Mbase + w * 32 + m * 16 + qr;
                atomicAdd(&out[row],     zv * (s0[m] + b2v));
                atomicAdd(&out[row + 8], zv * (s1[m] + b2v));
            }
        }
        __syncthreads();  // protect E before next tile's gather
    }
}

extern "C" void kernel_launch(void* const* d_in, const int* in_sizes, int n_in,
                              void* d_out, int out_size) {
    const int*   mains      = (const int*)  d_in[0];
    const int*   pairs      = (const int*)  d_in[1];
    const float* emb        = (const float*)d_in[2];
    const float* mw0        = (const float*)d_in[3];
    const float* mw1        = (const float*)d_in[4];
    const float* mw2        = (const float*)d_in[5];
    const float* mb0        = (const float*)d_in[6];
    const float* mb1        = (const float*)d_in[7];
    const float* mb2        = (const float*)d_in[8];
    const float* z_main     = (const float*)d_in[9];
    const float* pw0        = (const float*)d_in[10];
    const float* pw1        = (const float*)d_in[11];
    const float* pw2        = (const float*)d_in[12];
    const float* pb0        = (const float*)d_in[13];
    const float* pb1        = (const float*)d_in[14];
    const float* pb2        = (const float*)d_in[15];
    const float* z_pairs    = (const float*)d_in[16];
    const int*   pairs_list = (const int*)  d_in[17];
    const int*   feat_off   = (const int*)  d_in[18];
    float* out = (float*)d_out;

    static int configured = 0;
    if (!configured) {
        cudaFuncSetAttribute(dnamite_h16_kernel,
                             cudaFuncAttributeMaxDynamicSharedMemorySize, SMEM_TOTAL);
        configured = 1;
    }
    cudaMemsetAsync(out, 0, NB * sizeof(float), 0);
    dnamite_h16_kernel<<<NGROUPS, 128, SMEM_TOTAL>>>(
        mains, pairs, emb, mw0, mw1, mw2, mb0, mb1, mb2, z_main,
        pw0, pw1, pw2, pb0, pb1, pb2, z_pairs, pairs_list, feat_off, out);
}

// round 8
// speedup vs baseline: 6.2303x; 1.1581x over previous
#include <cuda_runtime.h>
#include <cuda_fp16.h>
#include <cstdint>

#define NB 512
#define NF 64
#define NP 2016
#define NE 32
#define NGROUPS (NP + NF)

// strides in 4B words (stride % 32 == 4 -> conflict-free fragment patterns)
#define SE  36   // E  [128 rows][32 h2-words + 4 pad]
#define SW0 36   // W0^T [128 n][32 kp-words + 4 pad]
#define SW1 68   // W1^T [128 n][64 kp-words + 4 pad]

// SMEM byte offsets
#define OFF_WT1 0        // 128*68*4 = 34816
#define OFF_WT0 34816    // 128*36*4 = 18432
#define OFF_E   53248    // 128*36*4 = 18432
#define OFF_B0  71680
#define OFF_B1  72192
#define OFF_W2  72704
#define SMEM_TOTAL 73216

__device__ __forceinline__ uint32_t pack_h2(float lo, float hi) {
    uint32_t d;
    asm("cvt.rn.f16x2.f32 %0, %1, %2;" : "=r"(d) : "f"(hi), "f"(lo));
    return d;
}

#define MMA_F16(d, a0, a1, a2, a3, bv0, bv1)                                   \
    asm volatile("mma.sync.aligned.m16n8k16.row.col.f32.f16.f16.f32 "          \
                 "{%0,%1,%2,%3}, {%4,%5,%6,%7}, {%8,%9}, {%0,%1,%2,%3};"       \
                 : "+f"((d)[0]), "+f"((d)[1]), "+f"((d)[2]), "+f"((d)[3])      \
                 : "r"(a0), "r"(a1), "r"(a2), "r"(a3), "r"(bv0), "r"(bv1))

__device__ __forceinline__ float smooth_z(float z) {
    float s = fmaf(-2.0f * z * z, z, fmaf(1.5f, z, 0.5f));
    s = (z <= -0.5f) ? 0.0f : s;
    s = (z >=  0.5f) ? 1.0f : s;
    return s;
}

extern __shared__ char smem_raw[];

__global__ __launch_bounds__(128, 3)
void dnamite_h16_kernel(const int*   __restrict__ mains,
                        const int*   __restrict__ pairs,
                        const float* __restrict__ emb,
                        const float* __restrict__ mw0, const float* __restrict__ mw1,
                        const float* __restrict__ mw2, const float* __restrict__ mb0,
                        const float* __restrict__ mb1, const float* __restrict__ mb2,
                        const float* __restrict__ z_main,
                        const float* __restrict__ pw0, const float* __restrict__ pw1,
                        const float* __restrict__ pw2, const float* __restrict__ pb0,
                        const float* __restrict__ pb1, const float* __restrict__ pb2,
                        const float* __restrict__ z_pairs,
                        const int*   __restrict__ pairs_list,
                        const int*   __restrict__ feat_off,
                        float*       __restrict__ out)
{
    uint32_t* WT1s = (uint32_t*)(smem_raw + OFF_WT1);
    uint32_t* WT0s = (uint32_t*)(smem_raw + OFF_WT0);
    uint32_t* E2   = (uint32_t*)(smem_raw + OFF_E);
    float*    b0s  = (float*)(smem_raw + OFF_B0);
    float*    b1s  = (float*)(smem_raw + OFF_B1);
    float*    w2s  = (float*)(smem_raw + OFF_W2);

    const int tid  = threadIdx.x;
    const int g    = blockIdx.x;
    const bool is_pair = (g < NP);

    const int lane = tid & 31;
    const int qr   = lane >> 2;   // 0..7
    const int qc   = lane & 3;    // 0..3
    const int w    = tid >> 5;    // warp 0..3 -> rows [w*32, w*32+32)

    const float *w0g, *w1g, *b0g, *b1g, *w2g;
    float b2v, zv;
    int offi = 0, offj = 0, K0, f_ = 0;
    if (is_pair) {
        K0  = 64;
        w0g = pw0 + (size_t)g * 64 * 128;
        w1g = pw1 + (size_t)g * 128 * 128;
        w2g = pw2 + (size_t)g * 128;
        b0g = pb0 + (size_t)g * 128;
        b1g = pb1 + (size_t)g * 128;
        b2v = pb2[g];
        zv  = smooth_z(z_pairs[g]);
        offi = feat_off[pairs_list[2 * g + 0]];
        offj = feat_off[pairs_list[2 * g + 1]];
    } else {
        f_  = g - NP;
        K0  = 32;
        w0g = mw0 + (size_t)f_ * 32 * 128;
        w1g = mw1 + (size_t)f_ * 128 * 128;
        w2g = mw2 + (size_t)f_ * 128;
        b0g = mb0 + (size_t)f_ * 128;
        b1g = mb1 + (size_t)f_ * 128;
        b2v = mb2[f_];
        zv  = smooth_z(z_main[f_]);
        offi = feat_off[f_];
    }

    // ---- weights -> SMEM as W^T [n][k-pair] in f16x2 ----
    for (int i = tid; i < 128 * (K0 >> 1); i += 128) {
        int n = i & 127, kp = i >> 7;
        float v0 = w0g[(2 * kp + 0) * 128 + n];
        float v1 = w0g[(2 * kp + 1) * 128 + n];
        WT0s[n * SW0 + kp] = pack_h2(v0, v1);
    }
    if (!is_pair) {  // zero-pad W0^T k-words 16..31 so unified K=64 path is safe
        for (int i = tid; i < 128 * 16; i += 128) {
            int n = i & 127, kp = i >> 7;
            WT0s[n * SW0 + 16 + kp] = 0u;
        }
    }
    for (int i = tid; i < 128 * 64; i += 128) {
        int n = i & 127, kp = i >> 7;
        float v0 = w1g[(2 * kp + 0) * 128 + n];
        float v1 = w1g[(2 * kp + 1) * 128 + n];
        WT1s[n * SW1 + kp] = pack_h2(v0, v1);
    }
    if (tid < 128) {
        b0s[tid] = b0g[tid];
        b1s[tid] = b1g[tid];
        w2s[tid] = w2g[tid];
    }

    #pragma unroll 1
    for (int mt = 0; mt < 4; mt++) {
        const int Mbase = mt * 128;

        // ---- gather E[128][64 h] as f16x2 words (pairs: concat; mains: pad 0) ----
        #pragma unroll
        for (int rr = tid; rr < 256; rr += 128) {
            const int r = rr >> 1, side = rr & 1;
            uint32_t* dst = E2 + r * SE + side * 16;
            if (is_pair || side == 0) {
                int bin, off;
                if (is_pair) {
                    bin = pairs[(((size_t)(Mbase + r)) * NP + g) * 2 + side];
                    off = side ? offj : offi;
                } else {
                    bin = mains[(size_t)(Mbase + r) * NF + f_];
                    off = offi;
                }
                const float4* src = (const float4*)(emb + (size_t)(off + bin) * NE);
                #pragma unroll
                for (int q = 0; q < 4; q++) {
                    float4 t0 = src[2 * q], t1 = src[2 * q + 1];
                    uint4 v;
                    v.x = pack_h2(t0.x, t0.y);
                    v.y = pack_h2(t0.z, t0.w);
                    v.z = pack_h2(t1.x, t1.y);
                    v.w = pack_h2(t1.z, t1.w);
                    *(uint4*)(dst + 4 * q) = v;
                }
            } else {  // mains, side==1: zero upper half
                uint4 z = {0u, 0u, 0u, 0u};
                #pragma unroll
                for (int q = 0; q < 4; q++) *(uint4*)(dst + 4 * q) = z;
            }
        }
        __syncthreads();

        // ---- layer 0 A fragments (2 m-subtiles x 4 k16-steps) ----
        uint32_t A0[2][4][4];
        #pragma unroll
        for (int m = 0; m < 2; m++) {
            const uint32_t* er0 = E2 + (w * 32 + m * 16 + qr) * SE + qc;
            const uint32_t* er1 = er0 + 8 * SE;
            #pragma unroll
            for (int ks = 0; ks < 4; ks++) {
                A0[m][ks][0] = er0[ks * 8];
                A0[m][ks][1] = er1[ks * 8];
                A0[m][ks][2] = er0[ks * 8 + 4];
                A0[m][ks][3] = er1[ks * 8 + 4];
            }
        }

        // ---- layer 0: H (registers, packed f16x2), N in 4 chunks of 32 ----
        uint32_t Hp0[2][16], Hp1[2][16];
        #pragma unroll
        for (int c = 0; c < 4; c++) {
            float acc[2][4][4];
            #pragma unroll
            for (int m = 0; m < 2; m++)
                #pragma unroll
                for (int t = 0; t < 4; t++)
                    #pragma unroll
                    for (int j = 0; j < 4; j++) acc[m][t][j] = 0.0f;

            const uint32_t* wb = WT0s + (c * 32 + qr) * SW0 + qc;
            #pragma unroll
            for (int ks = 0; ks < 4; ks++) {
                #pragma unroll
                for (int t = 0; t < 4; t++) {
                    uint32_t bv0 = wb[t * 8 * SW0 + ks * 8];
                    uint32_t bv1 = wb[t * 8 * SW0 + ks * 8 + 4];
                    MMA_F16(acc[0][t], A0[0][ks][0], A0[0][ks][1], A0[0][ks][2], A0[0][ks][3], bv0, bv1);
                    MMA_F16(acc[1][t], A0[1][ks][0], A0[1][ks][1], A0[1][ks][2], A0[1][ks][3], bv0, bv1);
                }
            }
            #pragma unroll
            for (int t = 0; t < 4; t++) {
                int tt  = c * 4 + t;
                int col = tt * 8 + 2 * qc;
                float ba = b0s[col], bb = b0s[col + 1];
                #pragma unroll
                for (int m = 0; m < 2; m++) {
                    Hp0[m][tt] = pack_h2(fmaxf(acc[m][t][0] + ba, 0.0f), fmaxf(acc[m][t][1] + bb, 0.0f));
                    Hp1[m][tt] = pack_h2(fmaxf(acc[m][t][2] + ba, 0.0f), fmaxf(acc[m][t][3] + bb, 0.0f));
                }
            }
        }

        // ---- layer 1 (A from registers), N in 4 chunks + fused epilogue ----
        float s0[2] = {0.0f, 0.0f}, s1[2] = {0.0f, 0.0f};
        #pragma unroll
        for (int c = 0; c < 4; c++) {
            float acc[2][4][4];
            #pragma unroll
            for (int m = 0; m < 2; m++)
                #pragma unroll
                for (int t = 0; t < 4; t++)
                    #pragma unroll
                    for (int j = 0; j < 4; j++) acc[m][t][j] = 0.0f;

            const uint32_t* wb = WT1s + (c * 32 + qr) * SW1 + qc;
            #pragma unroll
            for (int K = 0; K < 8; K++) {
                #pragma unroll
                for (int t = 0; t < 4; t++) {
                    uint32_t bv0 = wb[t * 8 * SW1 + K * 8];
                    uint32_t bv1 = wb[t * 8 * SW1 + K * 8 + 4];
                    MMA_F16(acc[0][t], Hp0[0][2 * K], Hp1[0][2 * K], Hp0[0][2 * K + 1], Hp1[0][2 * K + 1], bv0, bv1);
                    MMA_F16(acc[1][t], Hp0[1][2 * K], Hp1[1][2 * K], Hp0[1][2 * K + 1], Hp1[1][2 * K + 1], bv0, bv1);
                }
            }
            #pragma unroll
            for (int t = 0; t < 4; t++) {
                int col = (c * 4 + t) * 8 + 2 * qc;
                float ba = b1s[col], bb = b1s[col + 1];
                float wa = w2s[col], wb2 = w2s[col + 1];
                #pragma unroll
                for (int m = 0; m < 2; m++) {
                    s0[m] += fmaxf(acc[m][t][0] + ba, 0.0f) * wa + fmaxf(acc[m][t][1] + bb, 0.0f) * wb2;
                    s1[m] += fmaxf(acc[m][t][2] + ba, 0.0f) * wa + fmaxf(acc[m][t][3] + bb, 0.0f) * wb2;
                }
            }
        }

        // quad-reduce over qc and accumulate
        #pragma unroll
        for (int m = 0; m < 2; m++) {
            s0[m] += __shfl_xor_sync(0xFFFFFFFF, s0[m], 1);
            s0[m] += __shfl_xor_sync(0xFFFFFFFF, s0[m], 2);
            s1[m] += __shfl_xor_sync(0xFFFFFFFF, s1[m], 1);
            s1[m] += __shfl_xor_sync(0xFFFFFFFF, s1[m], 2);
        }
        if (qc == 0) {
            #pragma unroll
            for (int m = 0; m < 2; m++) {
                int row = Mbase + w * 32 + m * 16 + qr;
                atomicAdd(&out[row],     zv * (s0[m] + b2v));
                atomicAdd(&out[row + 8], zv * (s1[m] + b2v));
            }
        }
        __syncthreads();  // protect E before next tile's gather
    }
}

extern "C" void kernel_launch(void* const* d_in, const int* in_sizes, int n_in,
                              void* d_out, int out_size) {
    const int*   mains      = (const int*)  d_in[0];
    const int*   pairs      = (const int*)  d_in[1];
    const float* emb        = (const float*)d_in[2];
    const float* mw0        = (const float*)d_in[3];
    const float* mw1        = (const float*)d_in[4];
    const float* mw2        = (const float*)d_in[5];
    const float* mb0        = (const float*)d_in[6];
    const float* mb1        = (const float*)d_in[7];
    const float* mb2        = (const float*)d_in[8];
    const float* z_main     = (const float*)d_in[9];
    const float* pw0        = (const float*)d_in[10];
    const float* pw1        = (const float*)d_in[11];
    const float* pw2        = (const float*)d_in[12];
    const float* pb0        = (const float*)d_in[13];
    const float* pb1        = (const float*)d_in[14];
    const float* pb2        = (const float*)d_in[15];
    const float* z_pairs    = (const float*)d_in[16];
    const int*   pairs_list = (const int*)  d_in[17];
    const int*   feat_off   = (const int*)  d_in[18];
    float* out = (float*)d_out;

    static int configured = 0;
    if (!configured) {
        cudaFuncSetAttribute(dnamite_h16_kernel,
                             cudaFuncAttributeMaxDynamicSharedMemorySize, SMEM_TOTAL);
        configured = 1;
    }
    cudaMemsetAsync(out, 0, NB * sizeof(float), 0);
    dnamite_h16_kernel<<<NGROUPS, 128, SMEM_TOTAL>>>(
        mains, pairs, emb, mw0, mw1, mw2, mb0, mb1, mb2, z_main,
        pw0, pw1, pw2, pb0, pb1, pb2, z_pairs, pairs_list, feat_off, out);
}

// round 9
// speedup vs baseline: 7.1983x; 1.1554x over previous
#include <cuda_runtime.h>
#include <cuda_fp16.h>
#include <cstdint>

#define NB 512
#define NF 64
#define NP 2016
#define NE 32
#define NGROUPS (NP + NF)

// strides in 4B words (stride % 32 == 4 -> conflict-free fragment patterns)
#define SW0 36   // W0^T [128 n][32 kp-words + 4 pad]
#define SW1 68   // W1^T [128 n][64 kp-words + 4 pad]

// SMEM byte offsets
#define OFF_WT1 0        // 128*68*4 = 34816
#define OFF_WT0 34816    // 128*36*4 = 18432
#define OFF_B0  53248
#define OFF_B1  53760
#define OFF_W2  54272
#define SMEM_TOTAL 54784

__device__ __forceinline__ uint32_t pack_h2(float lo, float hi) {
    uint32_t d;
    asm("cvt.rn.f16x2.f32 %0, %1, %2;" : "=r"(d) : "f"(hi), "f"(lo));
    return d;
}

#define MMA_F16(d, a0, a1, a2, a3, bv0, bv1)                                   \
    asm volatile("mma.sync.aligned.m16n8k16.row.col.f32.f16.f16.f32 "          \
                 "{%0,%1,%2,%3}, {%4,%5,%6,%7}, {%8,%9}, {%0,%1,%2,%3};"       \
                 : "+f"((d)[0]), "+f"((d)[1]), "+f"((d)[2]), "+f"((d)[3])      \
                 : "r"(a0), "r"(a1), "r"(a2), "r"(a3), "r"(bv0), "r"(bv1))

__device__ __forceinline__ float smooth_z(float z) {
    float s = fmaf(-2.0f * z * z, z, fmaf(1.5f, z, 0.5f));
    s = (z <= -0.5f) ? 0.0f : s;
    s = (z >=  0.5f) ? 1.0f : s;
    return s;
}

extern __shared__ char smem_raw[];

__global__ __launch_bounds__(128, 3)
void dnamite_h16_kernel(const int*   __restrict__ mains,
                        const int*   __restrict__ pairs,
                        const float* __restrict__ emb,
                        const float* __restrict__ mw0, const float* __restrict__ mw1,
                        const float* __restrict__ mw2, const float* __restrict__ mb0,
                        const float* __restrict__ mb1, const float* __restrict__ mb2,
                        const float* __restrict__ z_main,
                        const float* __restrict__ pw0, const float* __restrict__ pw1,
                        const float* __restrict__ pw2, const float* __restrict__ pb0,
                        const float* __restrict__ pb1, const float* __restrict__ pb2,
                        const float* __restrict__ z_pairs,
                        const int*   __restrict__ pairs_list,
                        const int*   __restrict__ feat_off,
                        float*       __restrict__ out)
{
    uint32_t* WT1s = (uint32_t*)(smem_raw + OFF_WT1);
    uint32_t* WT0s = (uint32_t*)(smem_raw + OFF_WT0);
    float*    b0s  = (float*)(smem_raw + OFF_B0);
    float*    b1s  = (float*)(smem_raw + OFF_B1);
    float*    w2s  = (float*)(smem_raw + OFF_W2);

    const int tid  = threadIdx.x;
    const int g    = blockIdx.x;
    const bool is_pair = (g < NP);

    const int lane = tid & 31;
    const int qr   = lane >> 2;   // 0..7
    const int qc   = lane & 3;    // 0..3
    const int w    = tid >> 5;    // warp 0..3 -> rows [w*32, w*32+32)

    const float *w0g, *w1g, *b0g, *b1g, *w2g;
    float b2v, zv;
    int offi = 0, offj = 0, K0, f_ = 0;
    if (is_pair) {
        K0  = 64;
        w0g = pw0 + (size_t)g * 64 * 128;
        w1g = pw1 + (size_t)g * 128 * 128;
        w2g = pw2 + (size_t)g * 128;
        b0g = pb0 + (size_t)g * 128;
        b1g = pb1 + (size_t)g * 128;
        b2v = pb2[g];
        zv  = smooth_z(z_pairs[g]);
        offi = feat_off[pairs_list[2 * g + 0]];
        offj = feat_off[pairs_list[2 * g + 1]];
    } else {
        f_  = g - NP;
        K0  = 32;
        w0g = mw0 + (size_t)f_ * 32 * 128;
        w1g = mw1 + (size_t)f_ * 128 * 128;
        w2g = mw2 + (size_t)f_ * 128;
        b0g = mb0 + (size_t)f_ * 128;
        b1g = mb1 + (size_t)f_ * 128;
        b2v = mb2[f_];
        zv  = smooth_z(z_main[f_]);
        offi = feat_off[f_];
    }

    // ---- weights -> SMEM as W^T [n][k-pair] in f16x2 ----
    for (int i = tid; i < 128 * (K0 >> 1); i += 128) {
        int n = i & 127, kp = i >> 7;
        float v0 = w0g[(2 * kp + 0) * 128 + n];
        float v1 = w0g[(2 * kp + 1) * 128 + n];
        WT0s[n * SW0 + kp] = pack_h2(v0, v1);
    }
    if (!is_pair) {  // zero-pad W0^T k-words 16..31 so unified K=64 path is safe
        for (int i = tid; i < 128 * 16; i += 128) {
            int n = i & 127, kp = i >> 7;
            WT0s[n * SW0 + 16 + kp] = 0u;
        }
    }
    for (int i = tid; i < 128 * 64; i += 128) {
        int n = i & 127, kp = i >> 7;
        float v0 = w1g[(2 * kp + 0) * 128 + n];
        float v1 = w1g[(2 * kp + 1) * 128 + n];
        WT1s[n * SW1 + kp] = pack_h2(v0, v1);
    }
    if (tid < 128) {
        b0s[tid] = b0g[tid];
        b1s[tid] = b1g[tid];
        w2s[tid] = w2g[tid];
    }
    __syncthreads();   // weights visible; SMEM is read-only from here on

    #pragma unroll 1
    for (int mt = 0; mt < 4; mt++) {
        const int Mbase = mt * 128;

        // ---- A fragments straight from gmem (no SMEM, no barriers) ----
        // A0[m][ks]: a0=(row qr, k=16ks+2qc), a1=(row qr+8, same), a2/a3 = k+8
        uint32_t A0[2][4][4];
        #pragma unroll
        for (int m = 0; m < 2; m++) {
            #pragma unroll
            for (int t = 0; t < 2; t++) {
                const int row = Mbase + w * 32 + m * 16 + t * 8 + qr;
                const float* ei;
                const float* ej = nullptr;
                if (is_pair) {
                    int2 bp = *(const int2*)&pairs[((size_t)row * NP + g) * 2];
                    ei = emb + (size_t)(offi + bp.x) * NE;
                    ej = emb + (size_t)(offj + bp.y) * NE;
                } else {
                    int bin = mains[(size_t)row * NF + f_];
                    ei = emb + (size_t)(offi + bin) * NE;
                }
                const int k0 = 2 * qc;
                #pragma unroll
                for (int ks = 0; ks < 2; ks++) {   // k = 16ks + 2qc (< 32): side i
                    float2 x0 = *(const float2*)(ei + 16 * ks + k0);
                    float2 x1 = *(const float2*)(ei + 16 * ks + k0 + 8);
                    A0[m][ks][t]     = pack_h2(x0.x, x0.y);
                    A0[m][ks][t + 2] = pack_h2(x1.x, x1.y);
                }
                if (is_pair) {
                    #pragma unroll
                    for (int ks = 2; ks < 4; ks++) {  // k-32 in side j
                        float2 x0 = *(const float2*)(ej + 16 * (ks - 2) + k0);
                        float2 x1 = *(const float2*)(ej + 16 * (ks - 2) + k0 + 8);
                        A0[m][ks][t]     = pack_h2(x0.x, x0.y);
                        A0[m][ks][t + 2] = pack_h2(x1.x, x1.y);
                    }
                } else {
                    #pragma unroll
                    for (int ks = 2; ks < 4; ks++) {
                        A0[m][ks][t]     = 0u;
                        A0[m][ks][t + 2] = 0u;
                    }
                }
            }
        }

        // ---- layer 0: H (registers, packed f16x2), N in 4 chunks of 32 ----
        uint32_t Hp0[2][16], Hp1[2][16];
        #pragma unroll
        for (int c = 0; c < 4; c++) {
            float acc[2][4][4];
            #pragma unroll
            for (int m = 0; m < 2; m++)
                #pragma unroll
                for (int t = 0; t < 4; t++)
                    #pragma unroll
                    for (int j = 0; j < 4; j++) acc[m][t][j] = 0.0f;

            const uint32_t* wb = WT0s + (c * 32 + qr) * SW0 + qc;
            #pragma unroll
            for (int ks = 0; ks < 4; ks++) {
                #pragma unroll
                for (int t = 0; t < 4; t++) {
                    uint32_t bv0 = wb[t * 8 * SW0 + ks * 8];
                    uint32_t bv1 = wb[t * 8 * SW0 + ks * 8 + 4];
                    MMA_F16(acc[0][t], A0[0][ks][0], A0[0][ks][1], A0[0][ks][2], A0[0][ks][3], bv0, bv1);
                    MMA_F16(acc[1][t], A0[1][ks][0], A0[1][ks][1], A0[1][ks][2], A0[1][ks][3], bv0, bv1);
                }
            }
            #pragma unroll
            for (int t = 0; t < 4; t++) {
                int tt  = c * 4 + t;
                int col = tt * 8 + 2 * qc;
                float ba = b0s[col], bb = b0s[col + 1];
                #pragma unroll
                for (int m = 0; m < 2; m++) {
                    Hp0[m][tt] = pack_h2(fmaxf(acc[m][t][0] + ba, 0.0f), fmaxf(acc[m][t][1] + bb, 0.0f));
                    Hp1[m][tt] = pack_h2(fmaxf(acc[m][t][2] + ba, 0.0f), fmaxf(acc[m][t][3] + bb, 0.0f));
                }
            }
        }

        // ---- layer 1 (A from registers), N in 4 chunks + fused epilogue ----
        float s0[2] = {0.0f, 0.0f}, s1[2] = {0.0f, 0.0f};
        #pragma unroll
        for (int c = 0; c < 4; c++) {
            float acc[2][4][4];
            #pragma unroll
            for (int m = 0; m < 2; m++)
                #pragma unroll
                for (int t = 0; t < 4; t++)
                    #pragma unroll
                    for (int j = 0; j < 4; j++) acc[m][t][j] = 0.0f;

            const uint32_t* wb = WT1s + (c * 32 + qr) * SW1 + qc;
            #pragma unroll
            for (int K = 0; K < 8; K++) {
                #pragma unroll
                for (int t = 0; t < 4; t++) {
                    uint32_t bv0 = wb[t * 8 * SW1 + K * 8];
                    uint32_t bv1 = wb[t * 8 * SW1 + K * 8 + 4];
                    MMA_F16(acc[0][t], Hp0[0][2 * K], Hp1[0][2 * K], Hp0[0][2 * K + 1], Hp1[0][2 * K + 1], bv0, bv1);
                    MMA_F16(acc[1][t], Hp0[1][2 * K], Hp1[1][2 * K], Hp0[1][2 * K + 1], Hp1[1][2 * K + 1], bv0, bv1);
                }
            }
            #pragma unroll
            for (int t = 0; t < 4; t++) {
                int col = (c * 4 + t) * 8 + 2 * qc;
                float ba = b1s[col], bb = b1s[col + 1];
                float wa = w2s[col], wb2 = w2s[col + 1];
                #pragma unroll
                for (int m = 0; m < 2; m++) {
                    s0[m] += fmaxf(acc[m][t][0] + ba, 0.0f) * wa + fmaxf(acc[m][t][1] + bb, 0.0f) * wb2;
                    s1[m] += fmaxf(acc[m][t][2] + ba, 0.0f) * wa + fmaxf(acc[m][t][3] + bb, 0.0f) * wb2;
                }
            }
        }

        // quad-reduce over qc and accumulate
        #pragma unroll
        for (int m = 0; m < 2; m++) {
            s0[m] += __shfl_xor_sync(0xFFFFFFFF, s0[m], 1);
            s0[m] += __shfl_xor_sync(0xFFFFFFFF, s0[m], 2);
            s1[m] += __shfl_xor_sync(0xFFFFFFFF, s1[m], 1);
            s1[m] += __shfl_xor_sync(0xFFFFFFFF, s1[m], 2);
        }
        if (qc == 0) {
            #pragma unroll
            for (int m = 0; m < 2; m++) {
                int row = Mbase + w * 32 + m * 16 + qr;
                atomicAdd(&out[row],     zv * (s0[m] + b2v));
                atomicAdd(&out[row + 8], zv * (s1[m] + b2v));
            }
        }
    }
}

extern "C" void kernel_launch(void* const* d_in, const int* in_sizes, int n_in,
                              void* d_out, int out_size) {
    const int*   mains      = (const int*)  d_in[0];
    const int*   pairs      = (const int*)  d_in[1];
    const float* emb        = (const float*)d_in[2];
    const float* mw0        = (const float*)d_in[3];
    const float* mw1        = (const float*)d_in[4];
    const float* mw2        = (const float*)d_in[5];
    const float* mb0        = (const float*)d_in[6];
    const float* mb1        = (const float*)d_in[7];
    const float* mb2        = (const float*)d_in[8];
    const float* z_main     = (const float*)d_in[9];
    const float* pw0        = (const float*)d_in[10];
    const float* pw1        = (const float*)d_in[11];
    const float* pw2        = (const float*)d_in[12];
    const float* pb0        = (const float*)d_in[13];
    const float* pb1        = (const float*)d_in[14];
    const float* pb2        = (const float*)d_in[15];
    const float* z_pairs    = (const float*)d_in[16];
    const int*   pairs_list = (const int*)  d_in[17];
    const int*   feat_off   = (const int*)  d_in[18];
    float* out = (float*)d_out;

    static int configured = 0;
    if (!configured) {
        cudaFuncSetAttribute(dnamite_h16_kernel,
                             cudaFuncAttributeMaxDynamicSharedMemorySize, SMEM_TOTAL);
        configured = 1;
    }
    cudaMemsetAsync(out, 0, NB * sizeof(float), 0);
    dnamite_h16_kernel<<<NGROUPS, 128, SMEM_TOTAL>>>(
        mains, pairs, emb, mw0, mw1, mw2, mb0, mb1, mb2, z_main,
        pw0, pw1, pw2, pb0, pb1, pb2, z_pairs, pairs_list, feat_off, out);
}

// round 11
// speedup vs baseline: 7.3875x; 1.0263x over previous
#include <cuda_runtime.h>
#include <cuda_fp16.h>
#include <cstdint>

#define NB 512
#define NF 64
#define NP 2016
#define NE 32
#define NGROUPS (NP + NF)

// strides in 4B words (stride % 32 == 4 and row stride 16B-aligned for ldmatrix)
#define SW0 36   // W0^T [128 n][32 kp-words + 4 pad]   row = 144 B
#define SW1 68   // W1^T [128 n][64 kp-words + 4 pad]   row = 272 B

// SMEM byte offsets
#define OFF_WT1 0        // 128*68*4 = 34816
#define OFF_WT0 34816    // 128*36*4 = 18432
#define OFF_B0  53248
#define OFF_B1  53760
#define OFF_W2  54272
#define SMEM_TOTAL 54784

__device__ __forceinline__ uint32_t pack_h2(float lo, float hi) {
    uint32_t d;
    asm("cvt.rn.f16x2.f32 %0, %1, %2;" : "=r"(d) : "f"(hi), "f"(lo));
    return d;
}
__device__ __forceinline__ uint32_t smem_u32(const void* p) {
    uint32_t a;
    asm("{ .reg .u64 t; cvta.to.shared.u64 t, %1; cvt.u32.u64 %0, t; }" : "=r"(a) : "l"(p));
    return a;
}

#define MMA_F16(d, a0, a1, a2, a3, bv0, bv1)                                   \
    asm volatile("mma.sync.aligned.m16n8k16.row.col.f32.f16.f16.f32 "          \
                 "{%0,%1,%2,%3}, {%4,%5,%6,%7}, {%8,%9}, {%0,%1,%2,%3};"       \
                 : "+f"((d)[0]), "+f"((d)[1]), "+f"((d)[2]), "+f"((d)[3])      \
                 : "r"(a0), "r"(a1), "r"(a2), "r"(a3), "r"(bv0), "r"(bv1))

// x4: {b0,b1} = B-frag for n-tile t (kp+0 / kp+4), {b2,b3} = n-tile t+1
#define LDSM_X4(b0, b1, b2, b3, addr)                                          \
    asm volatile("ldmatrix.sync.aligned.m8n8.x4.shared.b16 {%0,%1,%2,%3}, [%4];" \
                 : "=r"(b0), "=r"(b1), "=r"(b2), "=r"(b3) : "r"(addr))

__device__ __forceinline__ float smooth_z(float z) {
    float s = fmaf(-2.0f * z * z, z, fmaf(1.5f, z, 0.5f));
    s = (z <= -0.5f) ? 0.0f : s;
    s = (z >=  0.5f) ? 1.0f : s;
    return s;
}

extern __shared__ char smem_raw[];

__global__ __launch_bounds__(128, 3)
void dnamite_h16_kernel(const int*   __restrict__ mains,
                        const int*   __restrict__ pairs,
                        const float* __restrict__ emb,
                        const float* __restrict__ mw0, const float* __restrict__ mw1,
                        const float* __restrict__ mw2, const float* __restrict__ mb0,
                        const float* __restrict__ mb1, const float* __restrict__ mb2,
                        const float* __restrict__ z_main,
                        const float* __restrict__ pw0, const float* __restrict__ pw1,
                        const float* __restrict__ pw2, const float* __restrict__ pb0,
                        const float* __restrict__ pb1, const float* __restrict__ pb2,
                        const float* __restrict__ z_pairs,
                        const int*   __restrict__ pairs_list,
                        const int*   __restrict__ feat_off,
                        float*       __restrict__ out)
{
    uint32_t* WT1s = (uint32_t*)(smem_raw + OFF_WT1);
    uint32_t* WT0s = (uint32_t*)(smem_raw + OFF_WT0);
    float*    b0s  = (float*)(smem_raw + OFF_B0);
    float*    b1s  = (float*)(smem_raw + OFF_B1);
    float*    w2s  = (float*)(smem_raw + OFF_W2);

    const int tid  = threadIdx.x;
    const int g    = blockIdx.x;
    const bool is_pair = (g < NP);

    const int lane = tid & 31;
    const int qr   = lane >> 2;   // 0..7
    const int qc   = lane & 3;    // 0..3
    const int w    = tid >> 5;    // warp 0..3 -> rows [w*32, w*32+32)

    // ldmatrix lane-address decomposition: matrix m = lane/8, row r = lane%8
    const int lm_thi = lane >> 4;        // 0 -> n-tile t, 1 -> n-tile t+1
    const int lm_tlo = (lane >> 3) & 1;  // 0 -> kp+0 (bv0), 1 -> kp+4 (bv1)
    const int lm_r   = lane & 7;

    const float *w0g, *w1g, *b0g, *b1g, *w2g;
    float b2v, zv;
    int offi = 0, offj = 0, K0, f_ = 0;
    if (is_pair) {
        K0  = 64;
        w0g = pw0 + (size_t)g * 64 * 128;
        w1g = pw1 + (size_t)g * 128 * 128;
        w2g = pw2 + (size_t)g * 128;
        b0g = pb0 + (size_t)g * 128;
        b1g = pb1 + (size_t)g * 128;
        b2v = pb2[g];
        zv  = smooth_z(z_pairs[g]);
        offi = feat_off[pairs_list[2 * g + 0]];
        offj = feat_off[pairs_list[2 * g + 1]];
    } else {
        f_  = g - NP;
        K0  = 32;
        w0g = mw0 + (size_t)f_ * 32 * 128;
        w1g = mw1 + (size_t)f_ * 128 * 128;
        w2g = mw2 + (size_t)f_ * 128;
        b0g = mb0 + (size_t)f_ * 128;
        b1g = mb1 + (size_t)f_ * 128;
        b2v = mb2[f_];
        zv  = smooth_z(z_main[f_]);
        offi = feat_off[f_];
    }

    // ---- weights -> SMEM as W^T [n][k-pair] in f16x2 ----
    for (int i = tid; i < 128 * (K0 >> 1); i += 128) {
        int n = i & 127, kp = i >> 7;
        float v0 = w0g[(2 * kp + 0) * 128 + n];
        float v1 = w0g[(2 * kp + 1) * 128 + n];
        WT0s[n * SW0 + kp] = pack_h2(v0, v1);
    }
    if (!is_pair) {  // zero-pad W0^T k-words 16..31 so unified K=64 path is safe
        for (int i = tid; i < 128 * 16; i += 128) {
            int n = i & 127, kp = i >> 7;
            WT0s[n * SW0 + 16 + kp] = 0u;
        }
    }
    for (int i = tid; i < 128 * 64; i += 128) {
        int n = i & 127, kp = i >> 7;
        float v0 = w1g[(2 * kp + 0) * 128 + n];
        float v1 = w1g[(2 * kp + 1) * 128 + n];
        WT1s[n * SW1 + kp] = pack_h2(v0, v1);
    }
    if (tid < 128) {
        b0s[tid] = b0g[tid];
        b1s[tid] = b1g[tid];
        w2s[tid] = w2g[tid];
    }
    __syncthreads();   // weights visible; SMEM is read-only from here on

    // per-lane ldmatrix base addresses (bytes)
    const uint32_t sb = smem_u32(smem_raw);
    const uint32_t lmw0 = sb + OFF_WT0 + 4u * ((uint32_t)(lm_thi * 8 + lm_r) * SW0 + lm_tlo * 4);
    const uint32_t lmw1 = sb + OFF_WT1 + 4u * ((uint32_t)(lm_thi * 8 + lm_r) * SW1 + lm_tlo * 4);

    #pragma unroll 1
    for (int mt = 0; mt < 4; mt++) {
        const int Mbase = mt * 128;

        // ---- A fragments straight from gmem (no SMEM, no barriers) ----
        uint32_t A0[2][4][4];
        #pragma unroll
        for (int m = 0; m < 2; m++) {
            #pragma unroll
            for (int t = 0; t < 2; t++) {
                const int row = Mbase + w * 32 + m * 16 + t * 8 + qr;
                const float* ei;
                const float* ej = nullptr;
                if (is_pair) {
                    int2 bp = *(const int2*)&pairs[((size_t)row * NP + g) * 2];
                    ei = emb + (size_t)(offi + bp.x) * NE;
                    ej = emb + (size_t)(offj + bp.y) * NE;
                } else {
                    int bin = mains[(size_t)row * NF + f_];
                    ei = emb + (size_t)(offi + bin) * NE;
                }
                const int k0 = 2 * qc;
                #pragma unroll
                for (int ks = 0; ks < 2; ks++) {
                    float2 x0 = *(const float2*)(ei + 16 * ks + k0);
                    float2 x1 = *(const float2*)(ei + 16 * ks + k0 + 8);
                    A0[m][ks][t]     = pack_h2(x0.x, x0.y);
                    A0[m][ks][t + 2] = pack_h2(x1.x, x1.y);
                }
                if (is_pair) {
                    #pragma unroll
                    for (int ks = 2; ks < 4; ks++) {
                        float2 x0 = *(const float2*)(ej + 16 * (ks - 2) + k0);
                        float2 x1 = *(const float2*)(ej + 16 * (ks - 2) + k0 + 8);
                        A0[m][ks][t]     = pack_h2(x0.x, x0.y);
                        A0[m][ks][t + 2] = pack_h2(x1.x, x1.y);
                    }
                } else {
                    #pragma unroll
                    for (int ks = 2; ks < 4; ks++) {
                        A0[m][ks][t]     = 0u;
                        A0[m][ks][t + 2] = 0u;
                    }
                }
            }
        }

        // ---- layer 0: H (registers, packed f16x2), N in 4 chunks of 32 ----
        uint32_t Hp0[2][16], Hp1[2][16];
        #pragma unroll
        for (int c = 0; c < 4; c++) {
            float acc[2][4][4];
            #pragma unroll
            for (int m = 0; m < 2; m++)
                #pragma unroll
                for (int t = 0; t < 4; t++)
                    #pragma unroll
                    for (int j = 0; j < 4; j++) acc[m][t][j] = 0.0f;

            #pragma unroll
            for (int ks = 0; ks < 4; ks++) {
                #pragma unroll
                for (int tp = 0; tp < 2; tp++) {   // n-tiles {2tp, 2tp+1}
                    uint32_t b0, b1, b2, b3;
                    LDSM_X4(b0, b1, b2, b3,
                            lmw0 + 4u * ((uint32_t)(c * 32 + tp * 16) * SW0 + ks * 8));
                    MMA_F16(acc[0][2 * tp],     A0[0][ks][0], A0[0][ks][1], A0[0][ks][2], A0[0][ks][3], b0, b1);
                    MMA_F16(acc[1][2 * tp],     A0[1][ks][0], A0[1][ks][1], A0[1][ks][2], A0[1][ks][3], b0, b1);
                    MMA_F16(acc[0][2 * tp + 1], A0[0][ks][0], A0[0][ks][1], A0[0][ks][2], A0[0][ks][3], b2, b3);
                    MMA_F16(acc[1][2 * tp + 1], A0[1][ks][0], A0[1][ks][1], A0[1][ks][2], A0[1][ks][3], b2, b3);
                }
            }
            #pragma unroll
            for (int t = 0; t < 4; t++) {
                int tt  = c * 4 + t;
                int col = tt * 8 + 2 * qc;
                float ba = b0s[col], bb = b0s[col + 1];
                #pragma unroll
                for (int m = 0; m < 2; m++) {
                    Hp0[m][tt] = pack_h2(fmaxf(acc[m][t][0] + ba, 0.0f), fmaxf(acc[m][t][1] + bb, 0.0f));
                    Hp1[m][tt] = pack_h2(fmaxf(acc[m][t][2] + ba, 0.0f), fmaxf(acc[m][t][3] + bb, 0.0f));
                }
            }
        }

        // ---- layer 1 (A from registers), N in 4 chunks + fused epilogue ----
        float s0[2] = {0.0f, 0.0f}, s1[2] = {0.0f, 0.0f};
        #pragma unroll
        for (int c = 0; c < 4; c++) {
            float acc[2][4][4];
            #pragma unroll
            for (int m = 0; m < 2; m++)
                #pragma unroll
                for (int t = 0; t < 4; t++)
                    #pragma unroll
                    for (int j = 0; j < 4; j++) acc[m][t][j] = 0.0f;

            #pragma unroll
            for (int K = 0; K < 8; K++) {
                #pragma unroll
                for (int tp = 0; tp < 2; tp++) {
                    uint32_t b0, b1, b2, b3;
                    LDSM_X4(b0, b1, b2, b3,
                            lmw1 + 4u * ((uint32_t)(c * 32 + tp * 16) * SW1 + K * 8));
                    MMA_F16(acc[0][2 * tp],     Hp0[0][2 * K], Hp1[0][2 * K], Hp0[0][2 * K + 1], Hp1[0][2 * K + 1], b0, b1);
                    MMA_F16(acc[1][2 * tp],     Hp0[1][2 * K], Hp1[1][2 * K], Hp0[1][2 * K + 1], Hp1[1][2 * K + 1], b0, b1);
                    MMA_F16(acc[0][2 * tp + 1], Hp0[0][2 * K], Hp1[0][2 * K], Hp0[0][2 * K + 1], Hp1[0][2 * K + 1], b2, b3);
                    MMA_F16(acc[1][2 * tp + 1], Hp0[1][2 * K], Hp1[1][2 * K], Hp0[1][2 * K + 1], Hp1[1][2 * K + 1], b2, b3);
                }
            }
            #pragma unroll
            for (int t = 0; t < 4; t++) {
                int col = (c * 4 + t) * 8 + 2 * qc;
                float ba = b1s[col], bb = b1s[col + 1];
                float wa = w2s[col], wb2 = w2s[col + 1];
                #pragma unroll
                for (int m = 0; m < 2; m++) {
                    s0[m] += fmaxf(acc[m][t][0] + ba, 0.0f) * wa + fmaxf(acc[m][t][1] + bb, 0.0f) * wb2;
                    s1[m] += fmaxf(acc[m][t][2] + ba, 0.0f) * wa + fmaxf(acc[m][t][3] + bb, 0.0f) * wb2;
                }
            }
        }

        // quad-reduce over qc and accumulate
        #pragma unroll
        for (int m = 0; m < 2; m++) {
            s0[m] += __shfl_xor_sync(0xFFFFFFFF, s0[m], 1);
            s0[m] += __shfl_xor_sync(0xFFFFFFFF, s0[m], 2);
            s1[m] += __shfl_xor_sync(0xFFFFFFFF, s1[m], 1);
            s1[m] += __shfl_xor_sync(0xFFFFFFFF, s1[m], 2);
        }
        if (qc == 0) {
            #pragma unroll
            for (int m = 0; m < 2; m++) {
                int row = Mbase + w * 32 + m * 16 + qr;
                atomicAdd(&out[row],     zv * (s0[m] + b2v));
                atomicAdd(&out[row + 8], zv * (s1[m] + b2v));
            }
        }
    }
}

extern "C" void kernel_launch(void* const* d_in, const int* in_sizes, int n_in,
                              void* d_out, int out_size) {
    const int*   mains      = (const int*)  d_in[0];
    const int*   pairs      = (const int*)  d_in[1];
    const float* emb        = (const float*)d_in[2];
    const float* mw0        = (const float*)d_in[3];
    const float* mw1        = (const float*)d_in[4];
    const float* mw2        = (const float*)d_in[5];
    const float* mb0        = (const float*)d_in[6];
    const float* mb1        = (const float*)d_in[7];
    const float* mb2        = (const float*)d_in[8];
    const float* z_main     = (const float*)d_in[9];
    const float* pw0        = (const float*)d_in[10];
    const float* pw1        = (const float*)d_in[11];
    const float* pw2        = (const float*)d_in[12];
    const float* pb0        = (const float*)d_in[13];
    const float* pb1        = (const float*)d_in[14];
    const float* pb2        = (const float*)d_in[15];
    const float* z_pairs    = (const float*)d_in[16];
    const int*   pairs_list = (const int*)  d_in[17];
    const int*   feat_off   = (const int*)  d_in[18];
    float* out = (float*)d_out;

    static int configured = 0;
    if (!configured) {
        cudaFuncSetAttribute(dnamite_h16_kernel,
                             cudaFuncAttributeMaxDynamicSharedMemorySize, SMEM_TOTAL);
        configured = 1;
    }
    cudaMemsetAsync(out, 0, NB * sizeof(float), 0);
    dnamite_h16_kernel<<<NGROUPS, 128, SMEM_TOTAL>>>(
        mains, pairs, emb, mw0, mw1, mw2, mb0, mb1, mb2, z_main,
        pw0, pw1, pw2, pb0, pb1, pb2, z_pairs, pairs_list, feat_off, out);
}